// round 1
// baseline (speedup 1.0000x reference)
#include <cuda_runtime.h>
#include <cstdint>

// ---------------- problem constants ----------------
constexpr int kB      = 128;
constexpr int kSeq    = 252;
constexpr int kWin    = 96;
constexpr int kLeads  = 12;
constexpr int kS      = 264;   // kSeq + kLeads
constexpr int kE      = 128;
constexpr int kH      = 8;
constexpr int kD      = 16;    // kE / kH
constexpr int kFF     = 512;
constexpr int kLayers = 12;
constexpr int kM      = kB * kS;   // 33792 tokens

// ---------------- scratch (device globals; no allocation allowed) -------------
__device__ float g_h   [kM * kE];   // residual stream
__device__ float g_buf1[kM * kFF];  // qkv (384-wide) / ff1 (512-wide)
__device__ float g_attn[kM * kE];   // attention output (pre O-proj)
__device__ float g_buf2[kM * kE];   // projection outputs

// =================== embedding ===================
// one block per token (b*kS + s), 128 threads = one output channel each
__global__ __launch_bounds__(128) void embed_kernel(
    const float* __restrict__ x, const int* __restrict__ t_idx,
    const int* __restrict__ sp_idx, const float* __restrict__ conv_w,
    const float* __restrict__ conv_b, const float* __restrict__ pos,
    const float* __restrict__ time_tab, const float* __restrict__ spat_tab,
    const float* __restrict__ cls)
{
    int token = blockIdx.x;
    int b = token / kS, s = token % kS;
    int e = threadIdx.x;
    float val;
    if (s < kLeads) {
        val = cls[s * kE + e] + pos[s * kE + e];
    } else {
        int l = s - kLeads;
        __shared__ float xs[kWin];
        if (e < kWin) xs[e] = x[((size_t)b * kSeq + l) * kWin + e];
        __syncthreads();
        float dot = 0.f;
        #pragma unroll 8
        for (int t = 0; t < kWin; t++) dot += xs[t] * conv_w[e * kWin + t];
        int ti = t_idx [b * kSeq + l];
        int si = sp_idx[b * kSeq + l];
        val = dot + conv_b[e] + pos[s * kE + e]
                  + time_tab[ti * kE + e] + spat_tab[si * kE + e];
    }
    g_h[(size_t)token * kE + e] = val;
}

// =================== tiled SGEMM: C[M,N] = A[M,K] @ W[N,K]^T + bias ===========
// BM=BN=64, BK=16, 256 threads, 4x4 micro-tile per thread.
// Requires M%64==0, N%64==0, K%16==0 (true for all call sites).
constexpr int BM = 64, BN = 64, BK = 16;

__global__ __launch_bounds__(256) void gemm_bias_kernel(
    const float* __restrict__ A, const float* __restrict__ W,
    const float* __restrict__ bias, float* __restrict__ C,
    int M, int N, int K, int relu)
{
    __shared__ __align__(16) float As[BK][BM];
    __shared__ __align__(16) float Ws[BK][BN];

    int tid = threadIdx.x;
    int tx = tid & 15;          // 0..15 -> 4 cols each
    int ty = tid >> 4;          // 0..15 -> 4 rows each
    int block_m = blockIdx.y * BM;
    int block_n = blockIdx.x * BN;

    // load mapping: thread -> one float4 of A-tile and one of W-tile
    int lm = tid >> 2;          // 0..63 (tile row)
    int lk = (tid & 3) << 2;    // 0,4,8,12 (tile col, float4)

    float acc[4][4] = {};

    for (int k0 = 0; k0 < K; k0 += BK) {
        float4 a4 = *reinterpret_cast<const float4*>(&A[(size_t)(block_m + lm) * K + k0 + lk]);
        float4 w4 = *reinterpret_cast<const float4*>(&W[(size_t)(block_n + lm) * K + k0 + lk]);
        As[lk + 0][lm] = a4.x; As[lk + 1][lm] = a4.y;
        As[lk + 2][lm] = a4.z; As[lk + 3][lm] = a4.w;
        Ws[lk + 0][lm] = w4.x; Ws[lk + 1][lm] = w4.y;
        Ws[lk + 2][lm] = w4.z; Ws[lk + 3][lm] = w4.w;
        __syncthreads();

        #pragma unroll
        for (int kk = 0; kk < BK; kk++) {
            float4 a = *reinterpret_cast<const float4*>(&As[kk][ty * 4]);
            float4 bq = *reinterpret_cast<const float4*>(&Ws[kk][tx * 4]);
            float av[4] = {a.x, a.y, a.z, a.w};
            float bv[4] = {bq.x, bq.y, bq.z, bq.w};
            #pragma unroll
            for (int i = 0; i < 4; i++)
                #pragma unroll
                for (int j = 0; j < 4; j++)
                    acc[i][j] += av[i] * bv[j];
        }
        __syncthreads();
    }

    #pragma unroll
    for (int i = 0; i < 4; i++) {
        int row = block_m + ty * 4 + i;
        #pragma unroll
        for (int j = 0; j < 4; j++) {
            int col = block_n + tx * 4 + j;
            float v = acc[i][j] + bias[col];
            if (relu) v = fmaxf(v, 0.f);
            C[(size_t)row * N + col] = v;
        }
    }
}

// =================== attention ===================
// one block per (b, head). K/V staged in smem once; 8 warps each own
// query rows w, w+8, ... (33 rows per warp). Scores in smem per warp.
__global__ __launch_bounds__(256) void attn_kernel(const float* __restrict__ qkv)
{
    __shared__ float Ks[kS][kD];
    __shared__ float Vs[kS][kD];
    __shared__ float Sc[8][kS];

    int bh = blockIdx.x;
    int b = bh / kH, head = bh % kH;
    int tid = threadIdx.x;
    const size_t tokbase = (size_t)b * kS;

    for (int i = tid; i < kS * kD; i += 256) {
        int s = i / kD, d = i % kD;
        size_t base = (tokbase + s) * 384 + head * kD;
        Ks[s][d] = qkv[base + 128 + d];
        Vs[s][d] = qkv[base + 256 + d];
    }
    __syncthreads();

    int w = tid >> 5, lane = tid & 31;

    for (int qrow = w; qrow < kS; qrow += 8) {
        float q[kD];
        size_t qbase = (tokbase + qrow) * 384 + head * kD;
        #pragma unroll
        for (int d = 0; d < kD; d++) q[d] = qkv[qbase + d];

        // scores
        for (int j = lane; j < kS; j += 32) {
            float dot = 0.f;
            #pragma unroll
            for (int d = 0; d < kD; d++) dot += q[d] * Ks[j][d];
            Sc[w][j] = dot * 0.25f;  // 1/sqrt(16)
        }
        __syncwarp();

        // max
        float m = -1e30f;
        for (int j = lane; j < kS; j += 32) m = fmaxf(m, Sc[w][j]);
        #pragma unroll
        for (int o = 16; o; o >>= 1) m = fmaxf(m, __shfl_xor_sync(0xffffffffu, m, o));

        // exp + sum
        float l = 0.f;
        for (int j = lane; j < kS; j += 32) {
            float p = __expf(Sc[w][j] - m);
            Sc[w][j] = p;
            l += p;
        }
        #pragma unroll
        for (int o = 16; o; o >>= 1) l += __shfl_xor_sync(0xffffffffu, l, o);
        __syncwarp();

        // weighted V sum
        float acc[kD];
        #pragma unroll
        for (int d = 0; d < kD; d++) acc[d] = 0.f;
        for (int j = lane; j < kS; j += 32) {
            float p = Sc[w][j];
            #pragma unroll
            for (int d = 0; d < kD; d++) acc[d] += p * Vs[j][d];
        }
        #pragma unroll
        for (int d = 0; d < kD; d++)
            #pragma unroll
            for (int o = 16; o; o >>= 1)
                acc[d] += __shfl_xor_sync(0xffffffffu, acc[d], o);

        if (lane == 0) {
            float inv = 1.0f / l;
            size_t obase = (tokbase + qrow) * kE + head * kD;
            #pragma unroll
            for (int d = 0; d < kD; d++) g_attn[obase + d] = acc[d] * inv;
        }
        __syncwarp();
    }
}

// =================== fused residual-add + LayerNorm ===================
// warp per row (128 cols, 4 per lane); in-place safe (row-local).
__global__ __launch_bounds__(256) void add_ln_kernel(
    const float* hin, const float* __restrict__ delta,
    const float* __restrict__ g, const float* __restrict__ beta,
    float* hout)
{
    int row  = blockIdx.x * 8 + (threadIdx.x >> 5);
    int lane = threadIdx.x & 31;
    size_t base = (size_t)row * kE;

    float4 hv = *reinterpret_cast<const float4*>(&hin  [base + lane * 4]);
    float4 dv = *reinterpret_cast<const float4*>(&delta[base + lane * 4]);
    float v0 = hv.x + dv.x, v1 = hv.y + dv.y, v2 = hv.z + dv.z, v3 = hv.w + dv.w;

    float s = v0 + v1 + v2 + v3;
    #pragma unroll
    for (int o = 16; o; o >>= 1) s += __shfl_xor_sync(0xffffffffu, s, o);
    float mean = s * (1.0f / kE);

    float d0 = v0 - mean, d1 = v1 - mean, d2 = v2 - mean, d3 = v3 - mean;
    float sq = d0 * d0 + d1 * d1 + d2 * d2 + d3 * d3;
    #pragma unroll
    for (int o = 16; o; o >>= 1) sq += __shfl_xor_sync(0xffffffffu, sq, o);
    float rstd = rsqrtf(sq * (1.0f / kE) + 1e-5f);

    float4 gv = *reinterpret_cast<const float4*>(&g   [lane * 4]);
    float4 bv = *reinterpret_cast<const float4*>(&beta[lane * 4]);
    float4 ov;
    ov.x = d0 * rstd * gv.x + bv.x;
    ov.y = d1 * rstd * gv.y + bv.y;
    ov.z = d2 * rstd * gv.z + bv.z;
    ov.w = d3 * rstd * gv.w + bv.w;
    *reinterpret_cast<float4*>(&hout[base + lane * 4]) = ov;
}

// =================== launch ===================
extern "C" void kernel_launch(void* const* d_in, const int* in_sizes, int n_in,
                              void* d_out, int out_size)
{
    const float* x        = (const float*)d_in[0];
    const int*   t_idx    = (const int*)  d_in[1];
    const int*   sp_idx   = (const int*)  d_in[2];
    const float* conv_w   = (const float*)d_in[3];
    const float* conv_b   = (const float*)d_in[4];
    const float* pos      = (const float*)d_in[5];
    const float* time_tab = (const float*)d_in[6];
    const float* spat_tab = (const float*)d_in[7];
    const float* cls      = (const float*)d_in[8];
    const float* Wqkv     = (const float*)d_in[9];
    const float* bqkv     = (const float*)d_in[10];
    const float* Wo       = (const float*)d_in[11];
    const float* bo       = (const float*)d_in[12];
    const float* W1       = (const float*)d_in[13];
    const float* b1       = (const float*)d_in[14];
    const float* W2       = (const float*)d_in[15];
    const float* b2       = (const float*)d_in[16];
    const float* ln1g     = (const float*)d_in[17];
    const float* ln1b     = (const float*)d_in[18];
    const float* ln2g     = (const float*)d_in[19];
    const float* ln2b     = (const float*)d_in[20];
    float* out = (float*)d_out;

    float *p_h, *p_buf1, *p_attn, *p_buf2;
    cudaGetSymbolAddress((void**)&p_h,    g_h);
    cudaGetSymbolAddress((void**)&p_buf1, g_buf1);
    cudaGetSymbolAddress((void**)&p_attn, g_attn);
    cudaGetSymbolAddress((void**)&p_buf2, g_buf2);

    embed_kernel<<<kM, 128>>>(x, t_idx, sp_idx, conv_w, conv_b, pos,
                              time_tab, spat_tab, cls);

    for (int i = 0; i < kLayers; i++) {
        // QKV: [M,128] -> [M,384]
        gemm_bias_kernel<<<dim3(384 / BN, kM / BM), 256>>>(
            p_h, Wqkv + (size_t)i * 384 * kE, bqkv + (size_t)i * 384,
            p_buf1, kM, 384, kE, 0);

        // attention -> g_attn
        attn_kernel<<<kB * kH, 256>>>(p_buf1);

        // O-proj: [M,128] -> [M,128]
        gemm_bias_kernel<<<dim3(kE / BN, kM / BM), 256>>>(
            p_attn, Wo + (size_t)i * kE * kE, bo + (size_t)i * kE,
            p_buf2, kM, kE, kE, 0);

        // h = LN(h + o)
        add_ln_kernel<<<kM / 8, 256>>>(p_h, p_buf2,
            ln1g + (size_t)i * kE, ln1b + (size_t)i * kE, p_h);

        // FFN1 + relu: [M,128] -> [M,512]
        gemm_bias_kernel<<<dim3(kFF / BN, kM / BM), 256>>>(
            p_h, W1 + (size_t)i * kFF * kE, b1 + (size_t)i * kFF,
            p_buf1, kM, kFF, kE, 1);

        // FFN2: [M,512] -> [M,128]
        gemm_bias_kernel<<<dim3(kE / BN, kM / BM), 256>>>(
            p_buf1, W2 + (size_t)i * kE * kFF, b2 + (size_t)i * kE,
            p_buf2, kM, kE, kFF, 0);

        // h = LN(h + ff); last layer writes straight to d_out
        float* dst = (i == kLayers - 1) ? out : p_h;
        add_ln_kernel<<<kM / 8, 256>>>(p_h, p_buf2,
            ln2g + (size_t)i * kE, ln2b + (size_t)i * kE, dst);
    }
}

// round 2
// speedup vs baseline: 2.2455x; 2.2455x over previous
#include <cuda_runtime.h>
#include <cstdint>

// ---------------- problem constants ----------------
constexpr int kB      = 128;
constexpr int kSeq    = 252;
constexpr int kWin    = 96;
constexpr int kLeads  = 12;
constexpr int kS      = 264;   // kSeq + kLeads
constexpr int kE      = 128;
constexpr int kH      = 8;
constexpr int kD      = 16;    // kE / kH
constexpr int kFF     = 512;
constexpr int kLayers = 12;
constexpr int kM      = kB * kS;   // 33792 tokens

// ---------------- scratch (device globals; no allocation allowed) -------------
__device__ float g_h   [kM * kE];   // residual stream
__device__ float g_buf1[kM * kFF];  // qkv (384-wide) / ff1 (512-wide)
__device__ float g_attn[kM * kE];   // attention output (pre O-proj)
__device__ float g_buf2[kM * kE];   // projection outputs

// =================== embedding ===================
__global__ __launch_bounds__(128) void embed_kernel(
    const float* __restrict__ x, const int* __restrict__ t_idx,
    const int* __restrict__ sp_idx, const float* __restrict__ conv_w,
    const float* __restrict__ conv_b, const float* __restrict__ pos,
    const float* __restrict__ time_tab, const float* __restrict__ spat_tab,
    const float* __restrict__ cls)
{
    int token = blockIdx.x;
    int b = token / kS, s = token % kS;
    int e = threadIdx.x;
    float val;
    if (s < kLeads) {
        val = cls[s * kE + e] + pos[s * kE + e];
    } else {
        int l = s - kLeads;
        __shared__ float xs[kWin];
        if (e < kWin) xs[e] = x[((size_t)b * kSeq + l) * kWin + e];
        __syncthreads();
        float dot = 0.f;
        #pragma unroll 8
        for (int t = 0; t < kWin; t++) dot += xs[t] * conv_w[e * kWin + t];
        int ti = t_idx [b * kSeq + l];
        int si = sp_idx[b * kSeq + l];
        val = dot + conv_b[e] + pos[s * kE + e]
                  + time_tab[ti * kE + e] + spat_tab[si * kE + e];
    }
    g_h[(size_t)token * kE + e] = val;
}

// =================== tiled SGEMM: C[M,N] = A[M,K] @ W[N,K]^T + bias ===========
// BM=128, BN=64, BK=16; 256 threads; 8x4 micro-tile; double-buffered smem.
// Requires M%128==0, N%64==0, K%16==0 (true for all call sites).
constexpr int BM = 128, BN = 64, BK = 16;

__global__ __launch_bounds__(256) void gemm_bias_kernel(
    const float* __restrict__ A, const float* __restrict__ W,
    const float* __restrict__ bias, float* __restrict__ C,
    int M, int N, int K, int relu)
{
    __shared__ __align__(16) float As[2][BK][BM];
    __shared__ __align__(16) float Ws[2][BK][BN];

    int tid = threadIdx.x;
    int bm = blockIdx.y * BM, bn = blockIdx.x * BN;

    int aRow = tid & 127;            // 0..127
    int aCol = (tid >> 7) << 3;      // 0 or 8
    int wRow = tid & 63;             // 0..63
    int wCol = (tid >> 6) << 2;      // 0,4,8,12

    const float* Aptr = A + (size_t)(bm + aRow) * K + aCol;
    const float* Wptr = W + (size_t)(bn + wRow) * K + wCol;

    // preload tile 0
    {
        float4 a0 = *(const float4*)Aptr;
        float4 a1 = *(const float4*)(Aptr + 4);
        float4 w0 = *(const float4*)Wptr;
        As[0][aCol+0][aRow] = a0.x; As[0][aCol+1][aRow] = a0.y;
        As[0][aCol+2][aRow] = a0.z; As[0][aCol+3][aRow] = a0.w;
        As[0][aCol+4][aRow] = a1.x; As[0][aCol+5][aRow] = a1.y;
        As[0][aCol+6][aRow] = a1.z; As[0][aCol+7][aRow] = a1.w;
        Ws[0][wCol+0][wRow] = w0.x; Ws[0][wCol+1][wRow] = w0.y;
        Ws[0][wCol+2][wRow] = w0.z; Ws[0][wCol+3][wRow] = w0.w;
    }
    __syncthreads();

    int ty = tid >> 4, tx = tid & 15;   // 16x16 thread grid: 8 rows x 4 cols each
    float acc[8][4] = {};
    int nIter = K >> 4;
    int buf = 0;

    for (int it = 0; it < nIter; it++) {
        float4 na0, na1, nw0;
        bool next = (it + 1 < nIter);
        if (next) {
            const float* Ap = Aptr + (it + 1) * BK;
            na0 = *(const float4*)Ap;
            na1 = *(const float4*)(Ap + 4);
            nw0 = *(const float4*)(Wptr + (it + 1) * BK);
        }
        #pragma unroll
        for (int kk = 0; kk < BK; kk++) {
            float4 av0 = *(const float4*)&As[buf][kk][ty * 8];
            float4 av1 = *(const float4*)&As[buf][kk][ty * 8 + 4];
            float4 bv  = *(const float4*)&Ws[buf][kk][tx * 4];
            float a[8] = {av0.x, av0.y, av0.z, av0.w, av1.x, av1.y, av1.z, av1.w};
            float bb[4] = {bv.x, bv.y, bv.z, bv.w};
            #pragma unroll
            for (int i = 0; i < 8; i++)
                #pragma unroll
                for (int j = 0; j < 4; j++)
                    acc[i][j] += a[i] * bb[j];
        }
        if (next) {
            int nb = buf ^ 1;
            As[nb][aCol+0][aRow] = na0.x; As[nb][aCol+1][aRow] = na0.y;
            As[nb][aCol+2][aRow] = na0.z; As[nb][aCol+3][aRow] = na0.w;
            As[nb][aCol+4][aRow] = na1.x; As[nb][aCol+5][aRow] = na1.y;
            As[nb][aCol+6][aRow] = na1.z; As[nb][aCol+7][aRow] = na1.w;
            Ws[nb][wCol+0][wRow] = nw0.x; Ws[nb][wCol+1][wRow] = nw0.y;
            Ws[nb][wCol+2][wRow] = nw0.z; Ws[nb][wCol+3][wRow] = nw0.w;
            __syncthreads();
            buf = nb;
        }
    }

    float4 bb4 = *(const float4*)&bias[bn + tx * 4];
    float bb[4] = {bb4.x, bb4.y, bb4.z, bb4.w};
    #pragma unroll
    for (int i = 0; i < 8; i++) {
        size_t row = bm + ty * 8 + i;
        float4 o;
        o.x = acc[i][0] + bb[0];
        o.y = acc[i][1] + bb[1];
        o.z = acc[i][2] + bb[2];
        o.w = acc[i][3] + bb[3];
        if (relu) {
            o.x = fmaxf(o.x, 0.f); o.y = fmaxf(o.y, 0.f);
            o.z = fmaxf(o.z, 0.f); o.w = fmaxf(o.w, 0.f);
        }
        *(float4*)&C[row * N + bn + tx * 4] = o;
    }
}

// =================== attention ===================
// One block per (b, head). K/V transposed in smem with odd stride (conflict-
// free). Each warp owns 33 query rows, processed 3 at a time; scores stay in
// registers; V accumulation split into two d-halves to bound register use.
constexpr int kSP = kS + 1;   // 265, odd stride -> conflict-free smem

__global__ __launch_bounds__(256) void attn_kernel(const float* __restrict__ qkv)
{
    __shared__ float Kt[kD][kSP];
    __shared__ float Vt[kD][kSP];

    int bh = blockIdx.x;
    int b = bh / kH, head = bh % kH;
    int tid = threadIdx.x;
    const size_t tokbase = (size_t)b * kS;

    // load K,V transposed: Kt[d][s]
    for (int i = tid; i < kS * kD; i += 256) {
        int s = i >> 4, d = i & 15;
        size_t base = (tokbase + s) * 384 + head * kD;
        Kt[d][s] = qkv[base + 128 + d];
        Vt[d][s] = qkv[base + 256 + d];
    }
    __syncthreads();

    int w = tid >> 5, lane = tid & 31;

    for (int g = 0; g < 11; g++) {
        int r0 = w * 33 + g * 3;
        const float* q0p = qkv + (tokbase + r0 + 0) * 384 + head * kD;
        const float* q1p = qkv + (tokbase + r0 + 1) * 384 + head * kD;
        const float* q2p = qkv + (tokbase + r0 + 2) * 384 + head * kD;

        float sc[3][9];
        #pragma unroll
        for (int r = 0; r < 3; r++)
            #pragma unroll
            for (int jj = 0; jj < 9; jj++) sc[r][jj] = 0.f;

        // scores: 3 rows share each K read
        #pragma unroll
        for (int d = 0; d < kD; d++) {
            float q0 = q0p[d], q1 = q1p[d], q2 = q2p[d];   // broadcast LDG (L1)
            #pragma unroll
            for (int jj = 0; jj < 9; jj++) {
                int j = lane + 32 * jj;
                if (j < kS) {
                    float k = Kt[d][j];
                    sc[0][jj] += q0 * k;
                    sc[1][jj] += q1 * k;
                    sc[2][jj] += q2 * k;
                }
            }
        }
        // mask out-of-range, scale
        #pragma unroll
        for (int r = 0; r < 3; r++) {
            #pragma unroll
            for (int jj = 0; jj < 9; jj++) {
                int j = lane + 32 * jj;
                sc[r][jj] = (j < kS) ? sc[r][jj] * 0.25f : -1e30f;
            }
        }

        // softmax (unnormalized p kept in sc; inv applied at the end)
        float inv[3];
        #pragma unroll
        for (int r = 0; r < 3; r++) {
            float m = -1e30f;
            #pragma unroll
            for (int jj = 0; jj < 9; jj++) m = fmaxf(m, sc[r][jj]);
            #pragma unroll
            for (int o = 16; o; o >>= 1) m = fmaxf(m, __shfl_xor_sync(0xffffffffu, m, o));
            float l = 0.f;
            #pragma unroll
            for (int jj = 0; jj < 9; jj++) {
                float p = __expf(sc[r][jj] - m);
                sc[r][jj] = p;
                l += p;
            }
            #pragma unroll
            for (int o = 16; o; o >>= 1) l += __shfl_xor_sync(0xffffffffu, l, o);
            inv[r] = 1.0f / l;
        }

        // P @ V, two d-halves of 8; V reads shared across the 3 rows
        #pragma unroll
        for (int half = 0; half < 2; half++) {
            float acc[3][8];
            #pragma unroll
            for (int r = 0; r < 3; r++)
                #pragma unroll
                for (int d = 0; d < 8; d++) acc[r][d] = 0.f;

            #pragma unroll
            for (int jj = 0; jj < 9; jj++) {
                int j = lane + 32 * jj;
                if (j < kS) {
                    float p0 = sc[0][jj], p1 = sc[1][jj], p2 = sc[2][jj];
                    #pragma unroll
                    for (int d = 0; d < 8; d++) {
                        float v = Vt[half * 8 + d][j];
                        acc[0][d] += p0 * v;
                        acc[1][d] += p1 * v;
                        acc[2][d] += p2 * v;
                    }
                }
            }
            #pragma unroll
            for (int r = 0; r < 3; r++)
                #pragma unroll
                for (int d = 0; d < 8; d++)
                    #pragma unroll
                    for (int o = 16; o; o >>= 1)
                        acc[r][d] += __shfl_xor_sync(0xffffffffu, acc[r][d], o);

            if (lane == 0) {
                #pragma unroll
                for (int r = 0; r < 3; r++) {
                    float4 o0, o1;
                    o0.x = acc[r][0] * inv[r]; o0.y = acc[r][1] * inv[r];
                    o0.z = acc[r][2] * inv[r]; o0.w = acc[r][3] * inv[r];
                    o1.x = acc[r][4] * inv[r]; o1.y = acc[r][5] * inv[r];
                    o1.z = acc[r][6] * inv[r]; o1.w = acc[r][7] * inv[r];
                    float* dst = g_attn + (tokbase + r0 + r) * kE + head * kD + half * 8;
                    *(float4*)(dst)     = o0;
                    *(float4*)(dst + 4) = o1;
                }
            }
        }
    }
}

// =================== fused residual-add + LayerNorm ===================
__global__ __launch_bounds__(256) void add_ln_kernel(
    const float* hin, const float* __restrict__ delta,
    const float* __restrict__ g, const float* __restrict__ beta,
    float* hout)
{
    int row  = blockIdx.x * 8 + (threadIdx.x >> 5);
    int lane = threadIdx.x & 31;
    size_t base = (size_t)row * kE;

    float4 hv = *reinterpret_cast<const float4*>(&hin  [base + lane * 4]);
    float4 dv = *reinterpret_cast<const float4*>(&delta[base + lane * 4]);
    float v0 = hv.x + dv.x, v1 = hv.y + dv.y, v2 = hv.z + dv.z, v3 = hv.w + dv.w;

    float s = v0 + v1 + v2 + v3;
    #pragma unroll
    for (int o = 16; o; o >>= 1) s += __shfl_xor_sync(0xffffffffu, s, o);
    float mean = s * (1.0f / kE);

    float d0 = v0 - mean, d1 = v1 - mean, d2 = v2 - mean, d3 = v3 - mean;
    float sq = d0 * d0 + d1 * d1 + d2 * d2 + d3 * d3;
    #pragma unroll
    for (int o = 16; o; o >>= 1) sq += __shfl_xor_sync(0xffffffffu, sq, o);
    float rstd = rsqrtf(sq * (1.0f / kE) + 1e-5f);

    float4 gv = *reinterpret_cast<const float4*>(&g   [lane * 4]);
    float4 bv = *reinterpret_cast<const float4*>(&beta[lane * 4]);
    float4 ov;
    ov.x = d0 * rstd * gv.x + bv.x;
    ov.y = d1 * rstd * gv.y + bv.y;
    ov.z = d2 * rstd * gv.z + bv.z;
    ov.w = d3 * rstd * gv.w + bv.w;
    *reinterpret_cast<float4*>(&hout[base + lane * 4]) = ov;
}

// =================== launch ===================
extern "C" void kernel_launch(void* const* d_in, const int* in_sizes, int n_in,
                              void* d_out, int out_size)
{
    const float* x        = (const float*)d_in[0];
    const int*   t_idx    = (const int*)  d_in[1];
    const int*   sp_idx   = (const int*)  d_in[2];
    const float* conv_w   = (const float*)d_in[3];
    const float* conv_b   = (const float*)d_in[4];
    const float* pos      = (const float*)d_in[5];
    const float* time_tab = (const float*)d_in[6];
    const float* spat_tab = (const float*)d_in[7];
    const float* cls      = (const float*)d_in[8];
    const float* Wqkv     = (const float*)d_in[9];
    const float* bqkv     = (const float*)d_in[10];
    const float* Wo       = (const float*)d_in[11];
    const float* bo       = (const float*)d_in[12];
    const float* W1       = (const float*)d_in[13];
    const float* b1       = (const float*)d_in[14];
    const float* W2       = (const float*)d_in[15];
    const float* b2       = (const float*)d_in[16];
    const float* ln1g     = (const float*)d_in[17];
    const float* ln1b     = (const float*)d_in[18];
    const float* ln2g     = (const float*)d_in[19];
    const float* ln2b     = (const float*)d_in[20];
    float* out = (float*)d_out;

    float *p_h, *p_buf1, *p_attn, *p_buf2;
    cudaGetSymbolAddress((void**)&p_h,    g_h);
    cudaGetSymbolAddress((void**)&p_buf1, g_buf1);
    cudaGetSymbolAddress((void**)&p_attn, g_attn);
    cudaGetSymbolAddress((void**)&p_buf2, g_buf2);

    embed_kernel<<<kM, 128>>>(x, t_idx, sp_idx, conv_w, conv_b, pos,
                              time_tab, spat_tab, cls);

    for (int i = 0; i < kLayers; i++) {
        // QKV: [M,128] -> [M,384]
        gemm_bias_kernel<<<dim3(384 / BN, kM / BM), 256>>>(
            p_h, Wqkv + (size_t)i * 384 * kE, bqkv + (size_t)i * 384,
            p_buf1, kM, 384, kE, 0);

        // attention -> g_attn
        attn_kernel<<<kB * kH, 256>>>(p_buf1);

        // O-proj: [M,128] -> [M,128]
        gemm_bias_kernel<<<dim3(kE / BN, kM / BM), 256>>>(
            p_attn, Wo + (size_t)i * kE * kE, bo + (size_t)i * kE,
            p_buf2, kM, kE, kE, 0);

        // h = LN(h + o)
        add_ln_kernel<<<kM / 8, 256>>>(p_h, p_buf2,
            ln1g + (size_t)i * kE, ln1b + (size_t)i * kE, p_h);

        // FFN1 + relu: [M,128] -> [M,512]
        gemm_bias_kernel<<<dim3(kFF / BN, kM / BM), 256>>>(
            p_h, W1 + (size_t)i * kFF * kE, b1 + (size_t)i * kFF,
            p_buf1, kM, kFF, kE, 1);

        // FFN2: [M,512] -> [M,128]
        gemm_bias_kernel<<<dim3(kE / BN, kM / BM), 256>>>(
            p_buf1, W2 + (size_t)i * kE * kFF, b2 + (size_t)i * kE,
            p_buf2, kM, kE, kFF, 0);

        // h = LN(h + ff); last layer writes straight to d_out
        float* dst = (i == kLayers - 1) ? out : p_h;
        add_ln_kernel<<<kM / 8, 256>>>(p_h, p_buf2,
            ln2g + (size_t)i * kE, ln2b + (size_t)i * kE, dst);
    }
}

// round 3
// speedup vs baseline: 2.4413x; 1.0872x over previous
#include <cuda_runtime.h>
#include <cstdint>

// ---------------- problem constants ----------------
constexpr int kB      = 128;
constexpr int kSeq    = 252;
constexpr int kWin    = 96;
constexpr int kLeads  = 12;
constexpr int kS      = 264;   // kSeq + kLeads
constexpr int kE      = 128;
constexpr int kH      = 8;
constexpr int kD      = 16;    // kE / kH
constexpr int kFF     = 512;
constexpr int kLayers = 12;
constexpr int kM      = kB * kS;   // 33792 tokens

// ---------------- scratch (device globals; no allocation allowed) -------------
__device__ float g_h   [kM * kE];   // residual stream
__device__ float g_buf1[kM * kFF];  // qkv (384-wide) / ff1 (512-wide)
__device__ float g_attn[kM * kE];   // attention output (pre O-proj)
__device__ float g_buf2[kM * kE];   // projection outputs

// =================== embedding ===================
__global__ __launch_bounds__(128) void embed_kernel(
    const float* __restrict__ x, const int* __restrict__ t_idx,
    const int* __restrict__ sp_idx, const float* __restrict__ conv_w,
    const float* __restrict__ conv_b, const float* __restrict__ pos,
    const float* __restrict__ time_tab, const float* __restrict__ spat_tab,
    const float* __restrict__ cls)
{
    int token = blockIdx.x;
    int b = token / kS, s = token % kS;
    int e = threadIdx.x;
    float val;
    if (s < kLeads) {
        val = cls[s * kE + e] + pos[s * kE + e];
    } else {
        int l = s - kLeads;
        __shared__ float xs[kWin];
        if (e < kWin) xs[e] = x[((size_t)b * kSeq + l) * kWin + e];
        __syncthreads();
        float dot = 0.f;
        #pragma unroll 8
        for (int t = 0; t < kWin; t++) dot += xs[t] * conv_w[e * kWin + t];
        int ti = t_idx [b * kSeq + l];
        int si = sp_idx[b * kSeq + l];
        val = dot + conv_b[e] + pos[s * kE + e]
                  + time_tab[ti * kE + e] + spat_tab[si * kE + e];
    }
    g_h[(size_t)token * kE + e] = val;
}

// =================== tf32 tensor-core GEMM (3xTF32 split) ===================
// C[M,N] = A[M,K] @ W[N,K]^T + bias.  BM=128 BN=64 BK=16, 256 thr (8 warps),
// warp tile 32x32 = 2x4 m16n8 tiles. acc += Ah*Bh + Ah*Bl + Al*Bh (fp32-grade).
// Requires M%128==0, N%64==0, K%16==0 (true for all call sites).
constexpr int BM = 128, BN = 64, BK = 16;
constexpr int ASTR = BK + 4;   // 20: conflict-free fragment LDS, 16B-aligned st

__device__ __forceinline__ uint32_t f2tf32(float x) {
    uint32_t r;
    asm("cvt.rna.tf32.f32 %0, %1;" : "=r"(r) : "f"(x));
    return r;
}
__device__ __forceinline__ float u2f(uint32_t x) { return __uint_as_float(x); }

#define MMA_TF32(d, a, b0, b1)                                                \
    asm volatile("mma.sync.aligned.m16n8k8.row.col.f32.tf32.tf32.f32 "        \
                 "{%0,%1,%2,%3}, {%4,%5,%6,%7}, {%8,%9}, {%0,%1,%2,%3};"      \
                 : "+f"(d[0]), "+f"(d[1]), "+f"(d[2]), "+f"(d[3])             \
                 : "r"(a[0]), "r"(a[1]), "r"(a[2]), "r"(a[3]),                \
                   "r"(b0), "r"(b1))

__global__ __launch_bounds__(256) void gemm_mma_kernel(
    const float* __restrict__ A, const float* __restrict__ W,
    const float* __restrict__ bias, float* __restrict__ C,
    int M, int N, int K, int relu)
{
    __shared__ uint32_t Ah[BM * ASTR];
    __shared__ uint32_t Al[BM * ASTR];
    __shared__ uint32_t Wh[BN * ASTR];
    __shared__ uint32_t Wl[BN * ASTR];

    int t = threadIdx.x;
    int bm = blockIdx.y * BM, bn = blockIdx.x * BN;

    // staging mapping: A -> 2 float4 per thread, W -> 1 float4 per thread
    int aRow = t >> 1;               // 0..127
    int aK   = (t & 1) * 8;          // 0 or 8
    int wRow = t >> 2;               // 0..63
    int wK   = (t & 3) * 4;          // 0,4,8,12

    const float* Aptr = A + (size_t)(bm + aRow) * K + aK;
    const float* Wptr = W + (size_t)(bn + wRow) * K + wK;

    int wid = t >> 5, lane = t & 31;
    int wm = (wid & 3) * 32;         // warp m offset in tile
    int wn = (wid >> 2) * 32;        // warp n offset in tile
    int grp = lane >> 2, q = lane & 3;

    float acc[2][4][4] = {};
    int nIter = K >> 4;

    float4 ra0 = *(const float4*)Aptr;
    float4 ra1 = *(const float4*)(Aptr + 4);
    float4 rw  = *(const float4*)Wptr;

    for (int it = 0; it < nIter; it++) {
        // convert + store current tile to smem
        {
            uint4 h, l;
            h.x = f2tf32(ra0.x); l.x = f2tf32(ra0.x - u2f(h.x));
            h.y = f2tf32(ra0.y); l.y = f2tf32(ra0.y - u2f(h.y));
            h.z = f2tf32(ra0.z); l.z = f2tf32(ra0.z - u2f(h.z));
            h.w = f2tf32(ra0.w); l.w = f2tf32(ra0.w - u2f(h.w));
            *(uint4*)&Ah[aRow * ASTR + aK] = h;
            *(uint4*)&Al[aRow * ASTR + aK] = l;
            h.x = f2tf32(ra1.x); l.x = f2tf32(ra1.x - u2f(h.x));
            h.y = f2tf32(ra1.y); l.y = f2tf32(ra1.y - u2f(h.y));
            h.z = f2tf32(ra1.z); l.z = f2tf32(ra1.z - u2f(h.z));
            h.w = f2tf32(ra1.w); l.w = f2tf32(ra1.w - u2f(h.w));
            *(uint4*)&Ah[aRow * ASTR + aK + 4] = h;
            *(uint4*)&Al[aRow * ASTR + aK + 4] = l;
            h.x = f2tf32(rw.x); l.x = f2tf32(rw.x - u2f(h.x));
            h.y = f2tf32(rw.y); l.y = f2tf32(rw.y - u2f(h.y));
            h.z = f2tf32(rw.z); l.z = f2tf32(rw.z - u2f(h.z));
            h.w = f2tf32(rw.w); l.w = f2tf32(rw.w - u2f(h.w));
            *(uint4*)&Wh[wRow * ASTR + wK] = h;
            *(uint4*)&Wl[wRow * ASTR + wK] = l;
        }
        __syncthreads();

        if (it + 1 < nIter) {
            const float* Ap = Aptr + (it + 1) * BK;
            ra0 = *(const float4*)Ap;
            ra1 = *(const float4*)(Ap + 4);
            rw  = *(const float4*)(Wptr + (it + 1) * BK);
        }

        #pragma unroll
        for (int ks = 0; ks < 2; ks++) {
            int k0 = ks * 8;
            uint32_t ah[2][4], al[2][4];
            #pragma unroll
            for (int mt = 0; mt < 2; mt++) {
                int rb = (wm + mt * 16 + grp) * ASTR + k0 + q;
                ah[mt][0] = Ah[rb];
                ah[mt][1] = Ah[rb + 8 * ASTR];
                ah[mt][2] = Ah[rb + 4];
                ah[mt][3] = Ah[rb + 8 * ASTR + 4];
                al[mt][0] = Al[rb];
                al[mt][1] = Al[rb + 8 * ASTR];
                al[mt][2] = Al[rb + 4];
                al[mt][3] = Al[rb + 8 * ASTR + 4];
            }
            #pragma unroll
            for (int nt = 0; nt < 4; nt++) {
                int nb = (wn + nt * 8 + grp) * ASTR + k0 + q;
                uint32_t bh0 = Wh[nb], bh1 = Wh[nb + 4];
                uint32_t bl0 = Wl[nb], bl1 = Wl[nb + 4];
                #pragma unroll
                for (int mt = 0; mt < 2; mt++) {
                    MMA_TF32(acc[mt][nt], ah[mt], bh0, bh1);
                    MMA_TF32(acc[mt][nt], ah[mt], bl0, bl1);
                    MMA_TF32(acc[mt][nt], al[mt], bh0, bh1);
                }
            }
        }
        __syncthreads();
    }

    // epilogue: bias (+relu), float2 stores
    #pragma unroll
    for (int mt = 0; mt < 2; mt++) {
        int row = bm + wm + mt * 16 + grp;
        #pragma unroll
        for (int nt = 0; nt < 4; nt++) {
            int col = bn + wn + nt * 8 + q * 2;
            float b0 = bias[col], b1 = bias[col + 1];
            float2 o0, o1;
            o0.x = acc[mt][nt][0] + b0; o0.y = acc[mt][nt][1] + b1;
            o1.x = acc[mt][nt][2] + b0; o1.y = acc[mt][nt][3] + b1;
            if (relu) {
                o0.x = fmaxf(o0.x, 0.f); o0.y = fmaxf(o0.y, 0.f);
                o1.x = fmaxf(o1.x, 0.f); o1.y = fmaxf(o1.y, 0.f);
            }
            *(float2*)&C[(size_t)row * N + col]       = o0;
            *(float2*)&C[(size_t)(row + 8) * N + col] = o1;
        }
    }
}

// =================== attention ===================
constexpr int kSP = kS + 1;   // 265, odd stride -> conflict-free smem

__global__ __launch_bounds__(256) void attn_kernel(const float* __restrict__ qkv)
{
    __shared__ float Kt[kD][kSP];
    __shared__ float Vt[kD][kSP];

    int bh = blockIdx.x;
    int b = bh / kH, head = bh % kH;
    int tid = threadIdx.x;
    const size_t tokbase = (size_t)b * kS;

    for (int i = tid; i < kS * kD; i += 256) {
        int s = i >> 4, d = i & 15;
        size_t base = (tokbase + s) * 384 + head * kD;
        Kt[d][s] = qkv[base + 128 + d];
        Vt[d][s] = qkv[base + 256 + d];
    }
    __syncthreads();

    int w = tid >> 5, lane = tid & 31;

    for (int g = 0; g < 11; g++) {
        int r0 = w * 33 + g * 3;
        const float* q0p = qkv + (tokbase + r0 + 0) * 384 + head * kD;
        const float* q1p = qkv + (tokbase + r0 + 1) * 384 + head * kD;
        const float* q2p = qkv + (tokbase + r0 + 2) * 384 + head * kD;

        float sc[3][9];
        #pragma unroll
        for (int r = 0; r < 3; r++)
            #pragma unroll
            for (int jj = 0; jj < 9; jj++) sc[r][jj] = 0.f;

        #pragma unroll
        for (int d = 0; d < kD; d++) {
            float q0 = q0p[d], q1 = q1p[d], q2 = q2p[d];
            #pragma unroll
            for (int jj = 0; jj < 9; jj++) {
                int j = lane + 32 * jj;
                if (j < kS) {
                    float k = Kt[d][j];
                    sc[0][jj] += q0 * k;
                    sc[1][jj] += q1 * k;
                    sc[2][jj] += q2 * k;
                }
            }
        }
        #pragma unroll
        for (int r = 0; r < 3; r++)
            #pragma unroll
            for (int jj = 0; jj < 9; jj++) {
                int j = lane + 32 * jj;
                sc[r][jj] = (j < kS) ? sc[r][jj] * 0.25f : -1e30f;
            }

        float inv[3];
        #pragma unroll
        for (int r = 0; r < 3; r++) {
            float m = -1e30f;
            #pragma unroll
            for (int jj = 0; jj < 9; jj++) m = fmaxf(m, sc[r][jj]);
            #pragma unroll
            for (int o = 16; o; o >>= 1) m = fmaxf(m, __shfl_xor_sync(0xffffffffu, m, o));
            float l = 0.f;
            #pragma unroll
            for (int jj = 0; jj < 9; jj++) {
                float p = __expf(sc[r][jj] - m);
                sc[r][jj] = p;
                l += p;
            }
            #pragma unroll
            for (int o = 16; o; o >>= 1) l += __shfl_xor_sync(0xffffffffu, l, o);
            inv[r] = 1.0f / l;
        }

        #pragma unroll
        for (int half = 0; half < 2; half++) {
            float acc[3][8];
            #pragma unroll
            for (int r = 0; r < 3; r++)
                #pragma unroll
                for (int d = 0; d < 8; d++) acc[r][d] = 0.f;

            #pragma unroll
            for (int jj = 0; jj < 9; jj++) {
                int j = lane + 32 * jj;
                if (j < kS) {
                    float p0 = sc[0][jj], p1 = sc[1][jj], p2 = sc[2][jj];
                    #pragma unroll
                    for (int d = 0; d < 8; d++) {
                        float v = Vt[half * 8 + d][j];
                        acc[0][d] += p0 * v;
                        acc[1][d] += p1 * v;
                        acc[2][d] += p2 * v;
                    }
                }
            }
            #pragma unroll
            for (int r = 0; r < 3; r++)
                #pragma unroll
                for (int d = 0; d < 8; d++)
                    #pragma unroll
                    for (int o = 16; o; o >>= 1)
                        acc[r][d] += __shfl_xor_sync(0xffffffffu, acc[r][d], o);

            if (lane == 0) {
                #pragma unroll
                for (int r = 0; r < 3; r++) {
                    float4 o0, o1;
                    o0.x = acc[r][0] * inv[r]; o0.y = acc[r][1] * inv[r];
                    o0.z = acc[r][2] * inv[r]; o0.w = acc[r][3] * inv[r];
                    o1.x = acc[r][4] * inv[r]; o1.y = acc[r][5] * inv[r];
                    o1.z = acc[r][6] * inv[r]; o1.w = acc[r][7] * inv[r];
                    float* dst = g_attn + (tokbase + r0 + r) * kE + head * kD + half * 8;
                    *(float4*)(dst)     = o0;
                    *(float4*)(dst + 4) = o1;
                }
            }
        }
    }
}

// =================== fused residual-add + LayerNorm ===================
__global__ __launch_bounds__(256) void add_ln_kernel(
    const float* hin, const float* __restrict__ delta,
    const float* __restrict__ g, const float* __restrict__ beta,
    float* hout)
{
    int row  = blockIdx.x * 8 + (threadIdx.x >> 5);
    int lane = threadIdx.x & 31;
    size_t base = (size_t)row * kE;

    float4 hv = *reinterpret_cast<const float4*>(&hin  [base + lane * 4]);
    float4 dv = *reinterpret_cast<const float4*>(&delta[base + lane * 4]);
    float v0 = hv.x + dv.x, v1 = hv.y + dv.y, v2 = hv.z + dv.z, v3 = hv.w + dv.w;

    float s = v0 + v1 + v2 + v3;
    #pragma unroll
    for (int o = 16; o; o >>= 1) s += __shfl_xor_sync(0xffffffffu, s, o);
    float mean = s * (1.0f / kE);

    float d0 = v0 - mean, d1 = v1 - mean, d2 = v2 - mean, d3 = v3 - mean;
    float sq = d0 * d0 + d1 * d1 + d2 * d2 + d3 * d3;
    #pragma unroll
    for (int o = 16; o; o >>= 1) sq += __shfl_xor_sync(0xffffffffu, sq, o);
    float rstd = rsqrtf(sq * (1.0f / kE) + 1e-5f);

    float4 gv = *reinterpret_cast<const float4*>(&g   [lane * 4]);
    float4 bv = *reinterpret_cast<const float4*>(&beta[lane * 4]);
    float4 ov;
    ov.x = d0 * rstd * gv.x + bv.x;
    ov.y = d1 * rstd * gv.y + bv.y;
    ov.z = d2 * rstd * gv.z + bv.z;
    ov.w = d3 * rstd * gv.w + bv.w;
    *reinterpret_cast<float4*>(&hout[base + lane * 4]) = ov;
}

// =================== launch ===================
extern "C" void kernel_launch(void* const* d_in, const int* in_sizes, int n_in,
                              void* d_out, int out_size)
{
    const float* x        = (const float*)d_in[0];
    const int*   t_idx    = (const int*)  d_in[1];
    const int*   sp_idx   = (const int*)  d_in[2];
    const float* conv_w   = (const float*)d_in[3];
    const float* conv_b   = (const float*)d_in[4];
    const float* pos      = (const float*)d_in[5];
    const float* time_tab = (const float*)d_in[6];
    const float* spat_tab = (const float*)d_in[7];
    const float* cls      = (const float*)d_in[8];
    const float* Wqkv     = (const float*)d_in[9];
    const float* bqkv     = (const float*)d_in[10];
    const float* Wo       = (const float*)d_in[11];
    const float* bo       = (const float*)d_in[12];
    const float* W1       = (const float*)d_in[13];
    const float* b1       = (const float*)d_in[14];
    const float* W2       = (const float*)d_in[15];
    const float* b2       = (const float*)d_in[16];
    const float* ln1g     = (const float*)d_in[17];
    const float* ln1b     = (const float*)d_in[18];
    const float* ln2g     = (const float*)d_in[19];
    const float* ln2b     = (const float*)d_in[20];
    float* out = (float*)d_out;

    float *p_h, *p_buf1, *p_attn, *p_buf2;
    cudaGetSymbolAddress((void**)&p_h,    g_h);
    cudaGetSymbolAddress((void**)&p_buf1, g_buf1);
    cudaGetSymbolAddress((void**)&p_attn, g_attn);
    cudaGetSymbolAddress((void**)&p_buf2, g_buf2);

    embed_kernel<<<kM, 128>>>(x, t_idx, sp_idx, conv_w, conv_b, pos,
                              time_tab, spat_tab, cls);

    for (int i = 0; i < kLayers; i++) {
        // QKV: [M,128] -> [M,384]
        gemm_mma_kernel<<<dim3(384 / BN, kM / BM), 256>>>(
            p_h, Wqkv + (size_t)i * 384 * kE, bqkv + (size_t)i * 384,
            p_buf1, kM, 384, kE, 0);

        // attention -> g_attn
        attn_kernel<<<kB * kH, 256>>>(p_buf1);

        // O-proj: [M,128] -> [M,128]
        gemm_mma_kernel<<<dim3(kE / BN, kM / BM), 256>>>(
            p_attn, Wo + (size_t)i * kE * kE, bo + (size_t)i * kE,
            p_buf2, kM, kE, kE, 0);

        // h = LN(h + o)
        add_ln_kernel<<<kM / 8, 256>>>(p_h, p_buf2,
            ln1g + (size_t)i * kE, ln1b + (size_t)i * kE, p_h);

        // FFN1 + relu: [M,128] -> [M,512]
        gemm_mma_kernel<<<dim3(kFF / BN, kM / BM), 256>>>(
            p_h, W1 + (size_t)i * kFF * kE, b1 + (size_t)i * kFF,
            p_buf1, kM, kFF, kE, 1);

        // FFN2: [M,512] -> [M,128]
        gemm_mma_kernel<<<dim3(kE / BN, kM / BM), 256>>>(
            p_buf1, W2 + (size_t)i * kE * kFF, b2 + (size_t)i * kE,
            p_buf2, kM, kE, kFF, 0);

        // h = LN(h + ff); last layer writes straight to d_out
        float* dst = (i == kLayers - 1) ? out : p_h;
        add_ln_kernel<<<kM / 8, 256>>>(p_h, p_buf2,
            ln2g + (size_t)i * kE, ln2b + (size_t)i * kE, dst);
    }
}

// round 4
// speedup vs baseline: 2.9884x; 1.2241x over previous
#include <cuda_runtime.h>
#include <cstdint>

// ---------------- problem constants ----------------
constexpr int kB      = 128;
constexpr int kSeq    = 252;
constexpr int kWin    = 96;
constexpr int kLeads  = 12;
constexpr int kS      = 264;   // kSeq + kLeads
constexpr int kE      = 128;
constexpr int kH      = 8;
constexpr int kD      = 16;    // kE / kH
constexpr int kFF     = 512;
constexpr int kLayers = 12;
constexpr int kM      = kB * kS;   // 33792 tokens

// ---------------- scratch (device globals; no allocation allowed) -------------
__device__ float g_h   [kM * kE];   // residual stream
__device__ float g_buf1[kM * kFF];  // qkv (384-wide) / ff1 (512-wide)
__device__ float g_attn[kM * kE];   // attention output (pre O-proj)
__device__ float g_buf2[kM * kE];   // projection outputs

// ---------------- tf32 helpers ----------------
__device__ __forceinline__ uint32_t f2tf32(float x) {
    uint32_t r;
    asm("cvt.rna.tf32.f32 %0, %1;" : "=r"(r) : "f"(x));
    return r;
}
__device__ __forceinline__ float u2f(uint32_t x) { return __uint_as_float(x); }

#define MMA_TF32(d, a, b0, b1)                                                \
    asm volatile("mma.sync.aligned.m16n8k8.row.col.f32.tf32.tf32.f32 "        \
                 "{%0,%1,%2,%3}, {%4,%5,%6,%7}, {%8,%9}, {%0,%1,%2,%3};"      \
                 : "+f"(d[0]), "+f"(d[1]), "+f"(d[2]), "+f"(d[3])             \
                 : "r"(a[0]), "r"(a[1]), "r"(a[2]), "r"(a[3]),                \
                   "r"(b0), "r"(b1))

// =================== embedding ===================
__global__ __launch_bounds__(128) void embed_kernel(
    const float* __restrict__ x, const int* __restrict__ t_idx,
    const int* __restrict__ sp_idx, const float* __restrict__ conv_w,
    const float* __restrict__ conv_b, const float* __restrict__ pos,
    const float* __restrict__ time_tab, const float* __restrict__ spat_tab,
    const float* __restrict__ cls)
{
    int token = blockIdx.x;
    int b = token / kS, s = token % kS;
    int e = threadIdx.x;
    float val;
    if (s < kLeads) {
        val = cls[s * kE + e] + pos[s * kE + e];
    } else {
        int l = s - kLeads;
        __shared__ float xs[kWin];
        if (e < kWin) xs[e] = x[((size_t)b * kSeq + l) * kWin + e];
        __syncthreads();
        float dot = 0.f;
        #pragma unroll 8
        for (int t = 0; t < kWin; t++) dot += xs[t] * conv_w[e * kWin + t];
        int ti = t_idx [b * kSeq + l];
        int si = sp_idx[b * kSeq + l];
        val = dot + conv_b[e] + pos[s * kE + e]
                  + time_tab[ti * kE + e] + spat_tab[si * kE + e];
    }
    g_h[(size_t)token * kE + e] = val;
}

// =================== tf32 tensor-core GEMM (3xTF32, ping-pong) ===============
// C[M,N] = A[M,K] @ W[N,K]^T + bias.  BM=128 BN=64 BK=16, 256 thr (8 warps),
// warp tile 32x32 = 2x4 m16n8 tiles. acc += Ah*Bh + Ah*Bl + Al*Bh.
constexpr int BM = 128, BN = 64, BK = 16;
constexpr int ASTR = BK + 4;   // 20
constexpr int GEMM_ABUF = BM * ASTR;   // 2560 words per buffer
constexpr int GEMM_WBUF = BN * ASTR;   // 1280 words per buffer
constexpr int GEMM_SMEM_BYTES = (4 * GEMM_ABUF + 4 * GEMM_WBUF) * 4;  // 61440

__device__ __forceinline__ void gemm_stage(
    uint32_t* __restrict__ AhB, uint32_t* __restrict__ AlB,
    uint32_t* __restrict__ WhB, uint32_t* __restrict__ WlB,
    int aRow, int aK, int wRow, int wK,
    float4 ra0, float4 ra1, float4 rw)
{
    uint4 h, l;
    h.x = f2tf32(ra0.x); l.x = f2tf32(ra0.x - u2f(h.x));
    h.y = f2tf32(ra0.y); l.y = f2tf32(ra0.y - u2f(h.y));
    h.z = f2tf32(ra0.z); l.z = f2tf32(ra0.z - u2f(h.z));
    h.w = f2tf32(ra0.w); l.w = f2tf32(ra0.w - u2f(h.w));
    *(uint4*)&AhB[aRow * ASTR + aK] = h;
    *(uint4*)&AlB[aRow * ASTR + aK] = l;
    h.x = f2tf32(ra1.x); l.x = f2tf32(ra1.x - u2f(h.x));
    h.y = f2tf32(ra1.y); l.y = f2tf32(ra1.y - u2f(h.y));
    h.z = f2tf32(ra1.z); l.z = f2tf32(ra1.z - u2f(h.z));
    h.w = f2tf32(ra1.w); l.w = f2tf32(ra1.w - u2f(h.w));
    *(uint4*)&AhB[aRow * ASTR + aK + 4] = h;
    *(uint4*)&AlB[aRow * ASTR + aK + 4] = l;
    h.x = f2tf32(rw.x); l.x = f2tf32(rw.x - u2f(h.x));
    h.y = f2tf32(rw.y); l.y = f2tf32(rw.y - u2f(h.y));
    h.z = f2tf32(rw.z); l.z = f2tf32(rw.z - u2f(h.z));
    h.w = f2tf32(rw.w); l.w = f2tf32(rw.w - u2f(h.w));
    *(uint4*)&WhB[wRow * ASTR + wK] = h;
    *(uint4*)&WlB[wRow * ASTR + wK] = l;
}

__global__ __launch_bounds__(256) void gemm_mma_kernel(
    const float* __restrict__ A, const float* __restrict__ W,
    const float* __restrict__ bias, float* __restrict__ C,
    int M, int N, int K, int relu)
{
    extern __shared__ uint32_t gsm[];
    uint32_t* Ah = gsm;                               // [2][GEMM_ABUF]
    uint32_t* Al = gsm + 2 * GEMM_ABUF;
    uint32_t* Wh = gsm + 4 * GEMM_ABUF;               // [2][GEMM_WBUF]
    uint32_t* Wl = gsm + 4 * GEMM_ABUF + 2 * GEMM_WBUF;

    int t = threadIdx.x;
    int bm = blockIdx.y * BM, bn = blockIdx.x * BN;

    int aRow = t >> 1;               // 0..127
    int aK   = (t & 1) * 8;          // 0 or 8
    int wRow = t >> 2;               // 0..63
    int wK   = (t & 3) * 4;          // 0,4,8,12

    const float* Aptr = A + (size_t)(bm + aRow) * K + aK;
    const float* Wptr = W + (size_t)(bn + wRow) * K + wK;

    int wid = t >> 5, lane = t & 31;
    int wm = (wid & 3) * 32;
    int wn = (wid >> 2) * 32;
    int grp = lane >> 2, q = lane & 3;

    float acc[2][4][4] = {};
    int nIter = K >> 4;

    float4 ra0 = *(const float4*)Aptr;
    float4 ra1 = *(const float4*)(Aptr + 4);
    float4 rw  = *(const float4*)Wptr;
    gemm_stage(Ah, Al, Wh, Wl, aRow, aK, wRow, wK, ra0, ra1, rw);
    __syncthreads();

    for (int it = 0; it < nIter; it++) {
        bool next = (it + 1 < nIter);
        if (next) {
            const float* Ap = Aptr + (it + 1) * BK;
            ra0 = *(const float4*)Ap;
            ra1 = *(const float4*)(Ap + 4);
            rw  = *(const float4*)(Wptr + (it + 1) * BK);
        }

        int buf = it & 1;
        const uint32_t* AhB = Ah + buf * GEMM_ABUF;
        const uint32_t* AlB = Al + buf * GEMM_ABUF;
        const uint32_t* WhB = Wh + buf * GEMM_WBUF;
        const uint32_t* WlB = Wl + buf * GEMM_WBUF;

        #pragma unroll
        for (int ks = 0; ks < 2; ks++) {
            int k0 = ks * 8;
            uint32_t ah[2][4], al[2][4];
            #pragma unroll
            for (int mt = 0; mt < 2; mt++) {
                int rb = (wm + mt * 16 + grp) * ASTR + k0 + q;
                ah[mt][0] = AhB[rb];
                ah[mt][1] = AhB[rb + 8 * ASTR];
                ah[mt][2] = AhB[rb + 4];
                ah[mt][3] = AhB[rb + 8 * ASTR + 4];
                al[mt][0] = AlB[rb];
                al[mt][1] = AlB[rb + 8 * ASTR];
                al[mt][2] = AlB[rb + 4];
                al[mt][3] = AlB[rb + 8 * ASTR + 4];
            }
            #pragma unroll
            for (int nt = 0; nt < 4; nt++) {
                int nb = (wn + nt * 8 + grp) * ASTR + k0 + q;
                uint32_t bh0 = WhB[nb], bh1 = WhB[nb + 4];
                uint32_t bl0 = WlB[nb], bl1 = WlB[nb + 4];
                #pragma unroll
                for (int mt = 0; mt < 2; mt++) {
                    MMA_TF32(acc[mt][nt], ah[mt], bh0, bh1);
                    MMA_TF32(acc[mt][nt], ah[mt], bl0, bl1);
                    MMA_TF32(acc[mt][nt], al[mt], bh0, bh1);
                }
            }
        }

        if (next) {
            int nb2 = (it + 1) & 1;
            gemm_stage(Ah + nb2 * GEMM_ABUF, Al + nb2 * GEMM_ABUF,
                       Wh + nb2 * GEMM_WBUF, Wl + nb2 * GEMM_WBUF,
                       aRow, aK, wRow, wK, ra0, ra1, rw);
            __syncthreads();
        }
    }

    #pragma unroll
    for (int mt = 0; mt < 2; mt++) {
        int row = bm + wm + mt * 16 + grp;
        #pragma unroll
        for (int nt = 0; nt < 4; nt++) {
            int col = bn + wn + nt * 8 + q * 2;
            float b0 = bias[col], b1 = bias[col + 1];
            float2 o0, o1;
            o0.x = acc[mt][nt][0] + b0; o0.y = acc[mt][nt][1] + b1;
            o1.x = acc[mt][nt][2] + b0; o1.y = acc[mt][nt][3] + b1;
            if (relu) {
                o0.x = fmaxf(o0.x, 0.f); o0.y = fmaxf(o0.y, 0.f);
                o1.x = fmaxf(o1.x, 0.f); o1.y = fmaxf(o1.y, 0.f);
            }
            *(float2*)&C[(size_t)row * N + col]       = o0;
            *(float2*)&C[(size_t)(row + 8) * N + col] = o1;
        }
    }
}

// =================== tensor-core attention (flash-style, 3xTF32) =============
// One block per (b,head), 8 warps. K/V staged in dynamic smem as interleaved
// (hi,lo) tf32 pairs, row stride 40 words (conflict-free B-frag loads).
// Each warp owns m16 q-tiles mt = wid, wid+8, (16 if wid==0). kv = 264 = 33 n8
// tiles, processed as 3 chunks of 11 with online softmax in C-fragments.
constexpr int KSTR = 2 * kD + 8;   // 40 words per token row
constexpr int ATT_SMEM_BYTES = 2 * kS * KSTR * 4;   // 84480

__global__ __launch_bounds__(256, 2) void attn_mma_kernel(const float* __restrict__ qkv)
{
    extern __shared__ uint32_t asm_[];
    uint32_t* Khl = asm_;
    uint32_t* Vhl = asm_ + kS * KSTR;

    int bh = blockIdx.x;
    int b = bh >> 3, head = bh & 7;
    int tid = threadIdx.x;
    const size_t tokbase = (size_t)b * kS;

    // stage K,V as tf32 hi/lo pairs
    for (int i = tid; i < kS * kD; i += 256) {
        int s = i >> 4, d = i & 15;
        const float* base = qkv + (tokbase + s) * 384 + head * kD;
        float kv = base[128 + d];
        float vv = base[256 + d];
        uint32_t kh = f2tf32(kv), vh = f2tf32(vv);
        Khl[s * KSTR + d * 2]     = kh;
        Khl[s * KSTR + d * 2 + 1] = f2tf32(kv - u2f(kh));
        Vhl[s * KSTR + d * 2]     = vh;
        Vhl[s * KSTR + d * 2 + 1] = f2tf32(vv - u2f(vh));
    }
    __syncthreads();

    int wid = tid >> 5, lane = tid & 31;
    int grp = lane >> 2, q = lane & 3;

    for (int mt = wid; mt < 17; mt += 8) {
        int r0 = mt * 16 + grp;         // always < 264
        int r1 = r0 + 8;                // may exceed for mt==16
        bool v1 = (r1 < kS);
        const float* q0p = qkv + (tokbase + r0) * 384 + head * kD;
        const float* q1p = qkv + (tokbase + (v1 ? r1 : 0)) * 384 + head * kD;

        // Q fragments (pre-scaled by 1/sqrt(D)=0.25, exact pow2), hi/lo split
        uint32_t qh[2][4], ql[2][4];
        #pragma unroll
        for (int ks = 0; ks < 2; ks++) {
            int k0 = ks * 8;
            float e[4];
            e[0] = 0.25f * q0p[k0 + q];
            e[1] = v1 ? 0.25f * q1p[k0 + q] : 0.f;
            e[2] = 0.25f * q0p[k0 + q + 4];
            e[3] = v1 ? 0.25f * q1p[k0 + q + 4] : 0.f;
            #pragma unroll
            for (int j = 0; j < 4; j++) {
                qh[ks][j] = f2tf32(e[j]);
                ql[ks][j] = f2tf32(e[j] - u2f(qh[ks][j]));
            }
        }

        float mA = -1e30f, mB = -1e30f, lA = 0.f, lB = 0.f;
        float O[2][4] = {};

        for (int ch = 0; ch < 3; ch++) {
            int n0 = ch * 88;

            // ---- scores S = Q @ K^T for 11 n8 tiles ----
            float sc[11][4];
            #pragma unroll
            for (int nt = 0; nt < 11; nt++) {
                sc[nt][0] = 0.f; sc[nt][1] = 0.f; sc[nt][2] = 0.f; sc[nt][3] = 0.f;
            }
            #pragma unroll
            for (int nt = 0; nt < 11; nt++) {
                const uint32_t* kb = &Khl[(n0 + nt * 8 + grp) * KSTR];
                #pragma unroll
                for (int ks = 0; ks < 2; ks++) {
                    int k0 = ks * 8;
                    uint2 b0 = *(const uint2*)&kb[(k0 + q) * 2];
                    uint2 b1 = *(const uint2*)&kb[(k0 + q + 4) * 2];
                    MMA_TF32(sc[nt], qh[ks], b0.x, b1.x);
                    MMA_TF32(sc[nt], qh[ks], b0.y, b1.y);
                    MMA_TF32(sc[nt], ql[ks], b0.x, b1.x);
                }
            }

            // ---- online softmax update ----
            float cmA = -1e30f, cmB = -1e30f;
            #pragma unroll
            for (int nt = 0; nt < 11; nt++) {
                cmA = fmaxf(cmA, fmaxf(sc[nt][0], sc[nt][1]));
                cmB = fmaxf(cmB, fmaxf(sc[nt][2], sc[nt][3]));
            }
            cmA = fmaxf(cmA, __shfl_xor_sync(0xffffffffu, cmA, 1));
            cmA = fmaxf(cmA, __shfl_xor_sync(0xffffffffu, cmA, 2));
            cmB = fmaxf(cmB, __shfl_xor_sync(0xffffffffu, cmB, 1));
            cmB = fmaxf(cmB, __shfl_xor_sync(0xffffffffu, cmB, 2));

            float mnA = fmaxf(mA, cmA), mnB = fmaxf(mB, cmB);
            float aA = __expf(mA - mnA), aB = __expf(mB - mnB);
            mA = mnA; mB = mnB;

            float sA = 0.f, sB = 0.f;
            #pragma unroll
            for (int nt = 0; nt < 11; nt++) {
                sc[nt][0] = __expf(sc[nt][0] - mA);
                sc[nt][1] = __expf(sc[nt][1] - mA);
                sc[nt][2] = __expf(sc[nt][2] - mB);
                sc[nt][3] = __expf(sc[nt][3] - mB);
                sA += sc[nt][0] + sc[nt][1];
                sB += sc[nt][2] + sc[nt][3];
            }
            sA += __shfl_xor_sync(0xffffffffu, sA, 1);
            sA += __shfl_xor_sync(0xffffffffu, sA, 2);
            sB += __shfl_xor_sync(0xffffffffu, sB, 1);
            sB += __shfl_xor_sync(0xffffffffu, sB, 2);
            lA = lA * aA + sA;
            lB = lB * aB + sB;
            #pragma unroll
            for (int n2 = 0; n2 < 2; n2++) {
                O[n2][0] *= aA; O[n2][1] *= aA;
                O[n2][2] *= aB; O[n2][3] *= aB;
            }

            // ---- O += P @ V ----
            int src0 = (lane & ~3) | (q >> 1);
            int src1 = src0 + 2;
            bool odd = (q & 1);
            #pragma unroll
            for (int kt = 0; kt < 11; kt++) {
                float p0 = sc[kt][0], p1 = sc[kt][1], p2 = sc[kt][2], p3 = sc[kt][3];
                float s0 = __shfl_sync(0xffffffffu, p0, src0);
                float s1 = __shfl_sync(0xffffffffu, p1, src0);
                float s2 = __shfl_sync(0xffffffffu, p2, src0);
                float s3 = __shfl_sync(0xffffffffu, p3, src0);
                float t0 = __shfl_sync(0xffffffffu, p0, src1);
                float t1 = __shfl_sync(0xffffffffu, p1, src1);
                float t2 = __shfl_sync(0xffffffffu, p2, src1);
                float t3 = __shfl_sync(0xffffffffu, p3, src1);
                float a0 = odd ? s1 : s0;
                float a1 = odd ? s3 : s2;
                float a2 = odd ? t1 : t0;
                float a3 = odd ? t3 : t2;
                uint32_t pah[4], pal[4];
                pah[0] = f2tf32(a0); pal[0] = f2tf32(a0 - u2f(pah[0]));
                pah[1] = f2tf32(a1); pal[1] = f2tf32(a1 - u2f(pah[1]));
                pah[2] = f2tf32(a2); pal[2] = f2tf32(a2 - u2f(pah[2]));
                pah[3] = f2tf32(a3); pal[3] = f2tf32(a3 - u2f(pah[3]));

                const uint32_t* vb = &Vhl[(n0 + kt * 8) * KSTR];
                #pragma unroll
                for (int n2 = 0; n2 < 2; n2++) {
                    uint2 b0 = *(const uint2*)&vb[q * KSTR + (n2 * 8 + grp) * 2];
                    uint2 b1 = *(const uint2*)&vb[(q + 4) * KSTR + (n2 * 8 + grp) * 2];
                    MMA_TF32(O[n2], pah, b0.x, b1.x);
                    MMA_TF32(O[n2], pah, b0.y, b1.y);
                    MMA_TF32(O[n2], pal, b0.x, b1.x);
                }
            }
        }

        // ---- finalize + store ----
        float iA = 1.0f / lA, iB = 1.0f / lB;
        #pragma unroll
        for (int n2 = 0; n2 < 2; n2++) {
            int col = head * kD + n2 * 8 + q * 2;
            float2 oA; oA.x = O[n2][0] * iA; oA.y = O[n2][1] * iA;
            *(float2*)&g_attn[(tokbase + r0) * kE + col] = oA;
            if (v1) {
                float2 oB; oB.x = O[n2][2] * iB; oB.y = O[n2][3] * iB;
                *(float2*)&g_attn[(tokbase + r1) * kE + col] = oB;
            }
        }
    }
}

// =================== fused residual-add + LayerNorm ===================
__global__ __launch_bounds__(256) void add_ln_kernel(
    const float* hin, const float* __restrict__ delta,
    const float* __restrict__ g, const float* __restrict__ beta,
    float* hout)
{
    int row  = blockIdx.x * 8 + (threadIdx.x >> 5);
    int lane = threadIdx.x & 31;
    size_t base = (size_t)row * kE;

    float4 hv = *reinterpret_cast<const float4*>(&hin  [base + lane * 4]);
    float4 dv = *reinterpret_cast<const float4*>(&delta[base + lane * 4]);
    float v0 = hv.x + dv.x, v1 = hv.y + dv.y, v2 = hv.z + dv.z, v3 = hv.w + dv.w;

    float s = v0 + v1 + v2 + v3;
    #pragma unroll
    for (int o = 16; o; o >>= 1) s += __shfl_xor_sync(0xffffffffu, s, o);
    float mean = s * (1.0f / kE);

    float d0 = v0 - mean, d1 = v1 - mean, d2 = v2 - mean, d3 = v3 - mean;
    float sq = d0 * d0 + d1 * d1 + d2 * d2 + d3 * d3;
    #pragma unroll
    for (int o = 16; o; o >>= 1) sq += __shfl_xor_sync(0xffffffffu, sq, o);
    float rstd = rsqrtf(sq * (1.0f / kE) + 1e-5f);

    float4 gv = *reinterpret_cast<const float4*>(&g   [lane * 4]);
    float4 bv = *reinterpret_cast<const float4*>(&beta[lane * 4]);
    float4 ov;
    ov.x = d0 * rstd * gv.x + bv.x;
    ov.y = d1 * rstd * gv.y + bv.y;
    ov.z = d2 * rstd * gv.z + bv.z;
    ov.w = d3 * rstd * gv.w + bv.w;
    *reinterpret_cast<float4*>(&hout[base + lane * 4]) = ov;
}

// =================== launch ===================
extern "C" void kernel_launch(void* const* d_in, const int* in_sizes, int n_in,
                              void* d_out, int out_size)
{
    const float* x        = (const float*)d_in[0];
    const int*   t_idx    = (const int*)  d_in[1];
    const int*   sp_idx   = (const int*)  d_in[2];
    const float* conv_w   = (const float*)d_in[3];
    const float* conv_b   = (const float*)d_in[4];
    const float* pos      = (const float*)d_in[5];
    const float* time_tab = (const float*)d_in[6];
    const float* spat_tab = (const float*)d_in[7];
    const float* cls      = (const float*)d_in[8];
    const float* Wqkv     = (const float*)d_in[9];
    const float* bqkv     = (const float*)d_in[10];
    const float* Wo       = (const float*)d_in[11];
    const float* bo       = (const float*)d_in[12];
    const float* W1       = (const float*)d_in[13];
    const float* b1       = (const float*)d_in[14];
    const float* W2       = (const float*)d_in[15];
    const float* b2       = (const float*)d_in[16];
    const float* ln1g     = (const float*)d_in[17];
    const float* ln1b     = (const float*)d_in[18];
    const float* ln2g     = (const float*)d_in[19];
    const float* ln2b     = (const float*)d_in[20];
    float* out = (float*)d_out;

    float *p_h, *p_buf1, *p_attn, *p_buf2;
    cudaGetSymbolAddress((void**)&p_h,    g_h);
    cudaGetSymbolAddress((void**)&p_buf1, g_buf1);
    cudaGetSymbolAddress((void**)&p_attn, g_attn);
    cudaGetSymbolAddress((void**)&p_buf2, g_buf2);

    cudaFuncSetAttribute(gemm_mma_kernel,
        cudaFuncAttributeMaxDynamicSharedMemorySize, GEMM_SMEM_BYTES);
    cudaFuncSetAttribute(attn_mma_kernel,
        cudaFuncAttributeMaxDynamicSharedMemorySize, ATT_SMEM_BYTES);

    embed_kernel<<<kM, 128>>>(x, t_idx, sp_idx, conv_w, conv_b, pos,
                              time_tab, spat_tab, cls);

    for (int i = 0; i < kLayers; i++) {
        // QKV: [M,128] -> [M,384]
        gemm_mma_kernel<<<dim3(384 / BN, kM / BM), 256, GEMM_SMEM_BYTES>>>(
            p_h, Wqkv + (size_t)i * 384 * kE, bqkv + (size_t)i * 384,
            p_buf1, kM, 384, kE, 0);

        // attention -> g_attn
        attn_mma_kernel<<<kB * kH, 256, ATT_SMEM_BYTES>>>(p_buf1);

        // O-proj: [M,128] -> [M,128]
        gemm_mma_kernel<<<dim3(kE / BN, kM / BM), 256, GEMM_SMEM_BYTES>>>(
            p_attn, Wo + (size_t)i * kE * kE, bo + (size_t)i * kE,
            p_buf2, kM, kE, kE, 0);

        // h = LN(h + o)
        add_ln_kernel<<<kM / 8, 256>>>(p_h, p_buf2,
            ln1g + (size_t)i * kE, ln1b + (size_t)i * kE, p_h);

        // FFN1 + relu: [M,128] -> [M,512]
        gemm_mma_kernel<<<dim3(kFF / BN, kM / BM), 256, GEMM_SMEM_BYTES>>>(
            p_h, W1 + (size_t)i * kFF * kE, b1 + (size_t)i * kFF,
            p_buf1, kM, kFF, kE, 1);

        // FFN2: [M,512] -> [M,128]
        gemm_mma_kernel<<<dim3(kE / BN, kM / BM), 256, GEMM_SMEM_BYTES>>>(
            p_buf1, W2 + (size_t)i * kE * kFF, b2 + (size_t)i * kE,
            p_buf2, kM, kE, kFF, 0);

        // h = LN(h + ff); last layer writes straight to d_out
        float* dst = (i == kLayers - 1) ? out : p_h;
        add_ln_kernel<<<kM / 8, 256>>>(p_h, p_buf2,
            ln2g + (size_t)i * kE, ln2b + (size_t)i * kE, dst);
    }
}

// round 5
// speedup vs baseline: 3.9661x; 1.3272x over previous
#include <cuda_runtime.h>
#include <cuda_bf16.h>
#include <cstdint>

// ---------------- problem constants ----------------
constexpr int kB      = 128;
constexpr int kSeq    = 252;
constexpr int kWin    = 96;
constexpr int kLeads  = 12;
constexpr int kS      = 264;   // kSeq + kLeads
constexpr int kE      = 128;
constexpr int kH      = 8;
constexpr int kD      = 16;    // kE / kH
constexpr int kFF     = 512;
constexpr int kLayers = 12;
constexpr int kM      = kB * kS;   // 33792 tokens

// ---------------- scratch (device globals; no allocation allowed) -------------
__device__ float g_h   [kM * kE];   // residual stream
__device__ float g_buf1[kM * kFF];  // qkv (384-wide) / ff1 (512-wide)
__device__ float g_attn[kM * kE];   // attention output (pre O-proj)
__device__ float g_buf2[kM * kE];   // projection outputs

// ---------------- bf16 split helpers ----------------
__device__ __forceinline__ float bhi(float x) {
    return __bfloat162float(__float2bfloat16(x));
}
__device__ __forceinline__ uint32_t packbf(float a, float b) {
    __nv_bfloat162 t;
    t.x = __float2bfloat16(a);
    t.y = __float2bfloat16(b);
    return *reinterpret_cast<uint32_t*>(&t);
}
// split two consecutive-k floats into packed bf16 hi and lo words
__device__ __forceinline__ void split2(float a, float b, uint32_t& h, uint32_t& l) {
    float ha = bhi(a), hb = bhi(b);
    h = packbf(a, b);
    l = packbf(a - ha, b - hb);
}

#define MMA_BF16(d, a, b0, b1)                                                \
    asm volatile("mma.sync.aligned.m16n8k16.row.col.f32.bf16.bf16.f32 "       \
                 "{%0,%1,%2,%3}, {%4,%5,%6,%7}, {%8,%9}, {%0,%1,%2,%3};"      \
                 : "+f"(d[0]), "+f"(d[1]), "+f"(d[2]), "+f"(d[3])             \
                 : "r"(a[0]), "r"(a[1]), "r"(a[2]), "r"(a[3]),                \
                   "r"(b0), "r"(b1))

#define MMA_BF16_K8(d, a0, a1, b0)                                            \
    asm volatile("mma.sync.aligned.m16n8k8.row.col.f32.bf16.bf16.f32 "        \
                 "{%0,%1,%2,%3}, {%4,%5}, {%6}, {%0,%1,%2,%3};"               \
                 : "+f"(d[0]), "+f"(d[1]), "+f"(d[2]), "+f"(d[3])             \
                 : "r"(a0), "r"(a1), "r"(b0))

// =================== embedding ===================
__global__ __launch_bounds__(128) void embed_kernel(
    const float* __restrict__ x, const int* __restrict__ t_idx,
    const int* __restrict__ sp_idx, const float* __restrict__ conv_w,
    const float* __restrict__ conv_b, const float* __restrict__ pos,
    const float* __restrict__ time_tab, const float* __restrict__ spat_tab,
    const float* __restrict__ cls)
{
    int token = blockIdx.x;
    int b = token / kS, s = token % kS;
    int e = threadIdx.x;
    float val;
    if (s < kLeads) {
        val = cls[s * kE + e] + pos[s * kE + e];
    } else {
        int l = s - kLeads;
        __shared__ float xs[kWin];
        if (e < kWin) xs[e] = x[((size_t)b * kSeq + l) * kWin + e];
        __syncthreads();
        float dot = 0.f;
        #pragma unroll 8
        for (int t = 0; t < kWin; t++) dot += xs[t] * conv_w[e * kWin + t];
        int ti = t_idx [b * kSeq + l];
        int si = sp_idx[b * kSeq + l];
        val = dot + conv_b[e] + pos[s * kE + e]
                  + time_tab[ti * kE + e] + spat_tab[si * kE + e];
    }
    g_h[(size_t)token * kE + e] = val;
}

// =================== bf16x3 tensor-core GEMM (ping-pong) =====================
// C[M,N] = A[M,K] @ W[N,K]^T + bias.  BM=128 BN=64 BK=16, 256 thr (8 warps),
// warp tile 32x32 = 2x4 m16n8 tiles, one k16 step per iter.
// acc += Ah*Bh + Ah*Bl + Al*Bh  (bf16 hi/lo split, fp32 accumulate).
constexpr int BM = 128, BN = 64, BK = 16;
constexpr int PSTR = 12;                 // uint32 (bf16-pair) row stride; 8 used
constexpr int GEMM_ABUF = BM * PSTR;     // 1536 words
constexpr int GEMM_WBUF = BN * PSTR;     // 768 words
constexpr int GEMM_SMEM_BYTES = 2 * (2 * GEMM_ABUF + 2 * GEMM_WBUF) * 4;  // 36864

__device__ __forceinline__ void gemm_stage(
    uint32_t* __restrict__ AhB, uint32_t* __restrict__ AlB,
    uint32_t* __restrict__ WhB, uint32_t* __restrict__ WlB,
    int aRow, int aP, int wRow, int wP,
    float4 ra0, float4 ra1, float4 rw)
{
    uint4 h, l;
    split2(ra0.x, ra0.y, h.x, l.x);
    split2(ra0.z, ra0.w, h.y, l.y);
    split2(ra1.x, ra1.y, h.z, l.z);
    split2(ra1.z, ra1.w, h.w, l.w);
    *(uint4*)&AhB[aRow * PSTR + aP] = h;
    *(uint4*)&AlB[aRow * PSTR + aP] = l;

    uint2 wh, wl;
    split2(rw.x, rw.y, wh.x, wl.x);
    split2(rw.z, rw.w, wh.y, wl.y);
    *(uint2*)&WhB[wRow * PSTR + wP] = wh;
    *(uint2*)&WlB[wRow * PSTR + wP] = wl;
}

__global__ __launch_bounds__(256) void gemm_mma_kernel(
    const float* __restrict__ A, const float* __restrict__ W,
    const float* __restrict__ bias, float* __restrict__ C,
    int M, int N, int K, int relu)
{
    extern __shared__ uint32_t gsm[];
    uint32_t* Ah = gsm;                               // [2][GEMM_ABUF]
    uint32_t* Al = gsm + 2 * GEMM_ABUF;
    uint32_t* Wh = gsm + 4 * GEMM_ABUF;               // [2][GEMM_WBUF]
    uint32_t* Wl = gsm + 4 * GEMM_ABUF + 2 * GEMM_WBUF;

    int t = threadIdx.x;
    int bm = blockIdx.y * BM, bn = blockIdx.x * BN;

    int aRow = t >> 1;               // 0..127
    int aK   = (t & 1) * 8;          // 0 or 8 (float idx)
    int aP   = aK >> 1;              // pair idx 0 or 4
    int wRow = t >> 2;               // 0..63
    int wK   = (t & 3) * 4;          // 0,4,8,12
    int wP   = wK >> 1;              // 0,2,4,6

    const float* Aptr = A + (size_t)(bm + aRow) * K + aK;
    const float* Wptr = W + (size_t)(bn + wRow) * K + wK;

    int wid = t >> 5, lane = t & 31;
    int wm = (wid & 3) * 32;
    int wn = (wid >> 2) * 32;
    int grp = lane >> 2, q = lane & 3;

    float acc[2][4][4] = {};
    int nIter = K >> 4;

    float4 ra0 = *(const float4*)Aptr;
    float4 ra1 = *(const float4*)(Aptr + 4);
    float4 rw  = *(const float4*)Wptr;
    gemm_stage(Ah, Al, Wh, Wl, aRow, aP, wRow, wP, ra0, ra1, rw);
    __syncthreads();

    for (int it = 0; it < nIter; it++) {
        bool next = (it + 1 < nIter);
        if (next) {
            const float* Ap = Aptr + (it + 1) * BK;
            ra0 = *(const float4*)Ap;
            ra1 = *(const float4*)(Ap + 4);
            rw  = *(const float4*)(Wptr + (it + 1) * BK);
        }

        int buf = it & 1;
        const uint32_t* AhB = Ah + buf * GEMM_ABUF;
        const uint32_t* AlB = Al + buf * GEMM_ABUF;
        const uint32_t* WhB = Wh + buf * GEMM_WBUF;
        const uint32_t* WlB = Wl + buf * GEMM_WBUF;

        uint32_t ah[2][4], al[2][4];
        #pragma unroll
        for (int mt = 0; mt < 2; mt++) {
            int rb = (wm + mt * 16 + grp) * PSTR + q;
            ah[mt][0] = AhB[rb];
            ah[mt][1] = AhB[rb + 8 * PSTR];
            ah[mt][2] = AhB[rb + 4];
            ah[mt][3] = AhB[rb + 8 * PSTR + 4];
            al[mt][0] = AlB[rb];
            al[mt][1] = AlB[rb + 8 * PSTR];
            al[mt][2] = AlB[rb + 4];
            al[mt][3] = AlB[rb + 8 * PSTR + 4];
        }
        #pragma unroll
        for (int nt = 0; nt < 4; nt++) {
            int nb = (wn + nt * 8 + grp) * PSTR + q;
            uint32_t bh0 = WhB[nb], bh1 = WhB[nb + 4];
            uint32_t bl0 = WlB[nb], bl1 = WlB[nb + 4];
            #pragma unroll
            for (int mt = 0; mt < 2; mt++) {
                MMA_BF16(acc[mt][nt], ah[mt], bh0, bh1);
                MMA_BF16(acc[mt][nt], ah[mt], bl0, bl1);
                MMA_BF16(acc[mt][nt], al[mt], bh0, bh1);
            }
        }

        if (next) {
            int nb2 = (it + 1) & 1;
            gemm_stage(Ah + nb2 * GEMM_ABUF, Al + nb2 * GEMM_ABUF,
                       Wh + nb2 * GEMM_WBUF, Wl + nb2 * GEMM_WBUF,
                       aRow, aP, wRow, wP, ra0, ra1, rw);
            __syncthreads();
        }
    }

    #pragma unroll
    for (int mt = 0; mt < 2; mt++) {
        int row = bm + wm + mt * 16 + grp;
        #pragma unroll
        for (int nt = 0; nt < 4; nt++) {
            int col = bn + wn + nt * 8 + q * 2;
            float b0 = bias[col], b1 = bias[col + 1];
            float2 o0, o1;
            o0.x = acc[mt][nt][0] + b0; o0.y = acc[mt][nt][1] + b1;
            o1.x = acc[mt][nt][2] + b0; o1.y = acc[mt][nt][3] + b1;
            if (relu) {
                o0.x = fmaxf(o0.x, 0.f); o0.y = fmaxf(o0.y, 0.f);
                o1.x = fmaxf(o1.x, 0.f); o1.y = fmaxf(o1.y, 0.f);
            }
            *(float2*)&C[(size_t)row * N + col]       = o0;
            *(float2*)&C[(size_t)(row + 8) * N + col] = o1;
        }
    }
}

// =================== bf16x3 tensor-core attention (flash-style) ==============
// One block per (b,head), 8 warps. K staged as bf16 hi/lo pairs along d
// (row stride 12 words, conflict-free); V staged transposed with pairs along
// kv (row stride 140 words). kv = 264 = 33 n8 tiles in 3 chunks of 11;
// P@V uses 5 k16 tiles + 1 k8 tile per chunk; the S C-fragment maps directly
// to the P A-fragment (zero shuffles).
constexpr int KSTRP = 12;                     // K row stride (uint32 pairs)
constexpr int VSTR  = 140;                    // Vt row stride (uint32 pairs)
constexpr int ATT_KWORDS = kS * KSTRP;        // 3168
constexpr int ATT_VWORDS = kD * VSTR;         // 2240
constexpr int ATT_SMEM_BYTES = (2 * ATT_KWORDS + 2 * ATT_VWORDS) * 4;  // 43264

__global__ __launch_bounds__(256, 2) void attn_mma_kernel(const float* __restrict__ qkv)
{
    extern __shared__ uint32_t asm_[];
    uint32_t* Kh  = asm_;
    uint32_t* Kl  = asm_ + ATT_KWORDS;
    uint32_t* Vth = asm_ + 2 * ATT_KWORDS;
    uint32_t* Vtl = asm_ + 2 * ATT_KWORDS + ATT_VWORDS;

    int bh = blockIdx.x;
    int b = bh >> 3, head = bh & 7;
    int tid = threadIdx.x;
    const size_t tokbase = (size_t)b * kS;

    // stage K (pairs along d) and V transposed (pairs along kv), hi/lo bf16
    __nv_bfloat16* Kh16  = (__nv_bfloat16*)Kh;
    __nv_bfloat16* Kl16  = (__nv_bfloat16*)Kl;
    __nv_bfloat16* Vth16 = (__nv_bfloat16*)Vth;
    __nv_bfloat16* Vtl16 = (__nv_bfloat16*)Vtl;
    for (int i = tid; i < kS * kD; i += 256) {
        int s = i >> 4, d = i & 15;
        const float* base = qkv + (tokbase + s) * 384 + head * kD;
        float kv = base[128 + d];
        float vv = base[256 + d];
        float kh = bhi(kv), vh = bhi(vv);
        int kidx = (s * KSTRP + (d >> 1)) * 2 + (d & 1);
        Kh16[kidx] = __float2bfloat16(kv);
        Kl16[kidx] = __float2bfloat16(kv - kh);
        int vidx = (d * VSTR + (s >> 1)) * 2 + (s & 1);
        Vth16[vidx] = __float2bfloat16(vv);
        Vtl16[vidx] = __float2bfloat16(vv - vh);
    }
    __syncthreads();

    int wid = tid >> 5, lane = tid & 31;
    int grp = lane >> 2, q = lane & 3;

    for (int mt = wid; mt < 17; mt += 8) {
        int r0 = mt * 16 + grp;         // always < 264
        int r1 = r0 + 8;                // may exceed for mt==16
        bool v1 = (r1 < kS);
        const float* q0p = qkv + (tokbase + r0) * 384 + head * kD;
        const float* q1p = qkv + (tokbase + (v1 ? r1 : 0)) * 384 + head * kD;

        // Q m16k16 fragment, pre-scaled by 1/sqrt(D)=0.25, bf16 hi/lo
        uint32_t qh[4], ql[4];
        {
            float2 e0 = *(const float2*)(q0p + 2 * q);
            float2 e2 = *(const float2*)(q0p + 2 * q + 8);
            float2 e1 = make_float2(0.f, 0.f), e3 = make_float2(0.f, 0.f);
            if (v1) {
                e1 = *(const float2*)(q1p + 2 * q);
                e3 = *(const float2*)(q1p + 2 * q + 8);
            }
            split2(0.25f * e0.x, 0.25f * e0.y, qh[0], ql[0]);
            split2(0.25f * e1.x, 0.25f * e1.y, qh[1], ql[1]);
            split2(0.25f * e2.x, 0.25f * e2.y, qh[2], ql[2]);
            split2(0.25f * e3.x, 0.25f * e3.y, qh[3], ql[3]);
        }

        float mA = -1e30f, mB = -1e30f, lA = 0.f, lB = 0.f;
        float O[2][4] = {};

        for (int ch = 0; ch < 3; ch++) {
            int n0 = ch * 88;
            int n0h = ch * 44;   // pair offset

            // ---- scores S = Q @ K^T, 11 n8 tiles (one k16 MMA set each) ----
            float sc[11][4];
            #pragma unroll
            for (int nt = 0; nt < 11; nt++) {
                sc[nt][0] = 0.f; sc[nt][1] = 0.f; sc[nt][2] = 0.f; sc[nt][3] = 0.f;
                int kb = (n0 + nt * 8 + grp) * KSTRP + q;
                uint32_t bh0 = Kh[kb], bh1 = Kh[kb + 4];
                uint32_t bl0 = Kl[kb], bl1 = Kl[kb + 4];
                MMA_BF16(sc[nt], qh, bh0, bh1);
                MMA_BF16(sc[nt], qh, bl0, bl1);
                MMA_BF16(sc[nt], ql, bh0, bh1);
            }

            // ---- online softmax update ----
            float cmA = -1e30f, cmB = -1e30f;
            #pragma unroll
            for (int nt = 0; nt < 11; nt++) {
                cmA = fmaxf(cmA, fmaxf(sc[nt][0], sc[nt][1]));
                cmB = fmaxf(cmB, fmaxf(sc[nt][2], sc[nt][3]));
            }
            cmA = fmaxf(cmA, __shfl_xor_sync(0xffffffffu, cmA, 1));
            cmA = fmaxf(cmA, __shfl_xor_sync(0xffffffffu, cmA, 2));
            cmB = fmaxf(cmB, __shfl_xor_sync(0xffffffffu, cmB, 1));
            cmB = fmaxf(cmB, __shfl_xor_sync(0xffffffffu, cmB, 2));

            float mnA = fmaxf(mA, cmA), mnB = fmaxf(mB, cmB);
            float aA = __expf(mA - mnA), aB = __expf(mB - mnB);
            mA = mnA; mB = mnB;

            float sA = 0.f, sB = 0.f;
            #pragma unroll
            for (int nt = 0; nt < 11; nt++) {
                sc[nt][0] = __expf(sc[nt][0] - mA);
                sc[nt][1] = __expf(sc[nt][1] - mA);
                sc[nt][2] = __expf(sc[nt][2] - mB);
                sc[nt][3] = __expf(sc[nt][3] - mB);
                sA += sc[nt][0] + sc[nt][1];
                sB += sc[nt][2] + sc[nt][3];
            }
            sA += __shfl_xor_sync(0xffffffffu, sA, 1);
            sA += __shfl_xor_sync(0xffffffffu, sA, 2);
            sB += __shfl_xor_sync(0xffffffffu, sB, 1);
            sB += __shfl_xor_sync(0xffffffffu, sB, 2);
            lA = lA * aA + sA;
            lB = lB * aB + sB;
            #pragma unroll
            for (int n2 = 0; n2 < 2; n2++) {
                O[n2][0] *= aA; O[n2][1] *= aA;
                O[n2][2] *= aB; O[n2][3] *= aB;
            }

            // ---- O += P @ V : 5 k16 tiles (pairs of n8 score tiles) ----
            #pragma unroll
            for (int kt = 0; kt < 5; kt++) {
                uint32_t pah[4], pal[4];
                split2(sc[2*kt][0],   sc[2*kt][1],   pah[0], pal[0]);
                split2(sc[2*kt][2],   sc[2*kt][3],   pah[1], pal[1]);
                split2(sc[2*kt+1][0], sc[2*kt+1][1], pah[2], pal[2]);
                split2(sc[2*kt+1][2], sc[2*kt+1][3], pah[3], pal[3]);
                int voff = n0h + kt * 8;
                #pragma unroll
                for (int n2 = 0; n2 < 2; n2++) {
                    int vb = (grp + n2 * 8) * VSTR + voff + q;
                    uint32_t bh0 = Vth[vb], bh1 = Vth[vb + 4];
                    uint32_t bl0 = Vtl[vb], bl1 = Vtl[vb + 4];
                    MMA_BF16(O[n2], pah, bh0, bh1);
                    MMA_BF16(O[n2], pah, bl0, bl1);
                    MMA_BF16(O[n2], pal, bh0, bh1);
                }
            }
            // ---- leftover n8 tile (tile 10) via k8 MMA ----
            {
                uint32_t a0h, a0l, a1h, a1l;
                split2(sc[10][0], sc[10][1], a0h, a0l);
                split2(sc[10][2], sc[10][3], a1h, a1l);
                int voff = n0h + 40;
                #pragma unroll
                for (int n2 = 0; n2 < 2; n2++) {
                    int vb = (grp + n2 * 8) * VSTR + voff + q;
                    uint32_t bh0 = Vth[vb];
                    uint32_t bl0 = Vtl[vb];
                    MMA_BF16_K8(O[n2], a0h, a1h, bh0);
                    MMA_BF16_K8(O[n2], a0h, a1h, bl0);
                    MMA_BF16_K8(O[n2], a0l, a1l, bh0);
                }
            }
        }

        // ---- finalize + store ----
        float iA = 1.0f / lA, iB = 1.0f / lB;
        #pragma unroll
        for (int n2 = 0; n2 < 2; n2++) {
            int col = head * kD + n2 * 8 + q * 2;
            float2 oA; oA.x = O[n2][0] * iA; oA.y = O[n2][1] * iA;
            *(float2*)&g_attn[(tokbase + r0) * kE + col] = oA;
            if (v1) {
                float2 oB; oB.x = O[n2][2] * iB; oB.y = O[n2][3] * iB;
                *(float2*)&g_attn[(tokbase + r1) * kE + col] = oB;
            }
        }
    }
}

// =================== fused residual-add + LayerNorm ===================
__global__ __launch_bounds__(256) void add_ln_kernel(
    const float* hin, const float* __restrict__ delta,
    const float* __restrict__ g, const float* __restrict__ beta,
    float* hout)
{
    int row  = blockIdx.x * 8 + (threadIdx.x >> 5);
    int lane = threadIdx.x & 31;
    size_t base = (size_t)row * kE;

    float4 hv = *reinterpret_cast<const float4*>(&hin  [base + lane * 4]);
    float4 dv = *reinterpret_cast<const float4*>(&delta[base + lane * 4]);
    float v0 = hv.x + dv.x, v1 = hv.y + dv.y, v2 = hv.z + dv.z, v3 = hv.w + dv.w;

    float s = v0 + v1 + v2 + v3;
    #pragma unroll
    for (int o = 16; o; o >>= 1) s += __shfl_xor_sync(0xffffffffu, s, o);
    float mean = s * (1.0f / kE);

    float d0 = v0 - mean, d1 = v1 - mean, d2 = v2 - mean, d3 = v3 - mean;
    float sq = d0 * d0 + d1 * d1 + d2 * d2 + d3 * d3;
    #pragma unroll
    for (int o = 16; o; o >>= 1) sq += __shfl_xor_sync(0xffffffffu, sq, o);
    float rstd = rsqrtf(sq * (1.0f / kE) + 1e-5f);

    float4 gv = *reinterpret_cast<const float4*>(&g   [lane * 4]);
    float4 bv = *reinterpret_cast<const float4*>(&beta[lane * 4]);
    float4 ov;
    ov.x = d0 * rstd * gv.x + bv.x;
    ov.y = d1 * rstd * gv.y + bv.y;
    ov.z = d2 * rstd * gv.z + bv.z;
    ov.w = d3 * rstd * gv.w + bv.w;
    *reinterpret_cast<float4*>(&hout[base + lane * 4]) = ov;
}

// =================== launch ===================
extern "C" void kernel_launch(void* const* d_in, const int* in_sizes, int n_in,
                              void* d_out, int out_size)
{
    const float* x        = (const float*)d_in[0];
    const int*   t_idx    = (const int*)  d_in[1];
    const int*   sp_idx   = (const int*)  d_in[2];
    const float* conv_w   = (const float*)d_in[3];
    const float* conv_b   = (const float*)d_in[4];
    const float* pos      = (const float*)d_in[5];
    const float* time_tab = (const float*)d_in[6];
    const float* spat_tab = (const float*)d_in[7];
    const float* cls      = (const float*)d_in[8];
    const float* Wqkv     = (const float*)d_in[9];
    const float* bqkv     = (const float*)d_in[10];
    const float* Wo       = (const float*)d_in[11];
    const float* bo       = (const float*)d_in[12];
    const float* W1       = (const float*)d_in[13];
    const float* b1       = (const float*)d_in[14];
    const float* W2       = (const float*)d_in[15];
    const float* b2       = (const float*)d_in[16];
    const float* ln1g     = (const float*)d_in[17];
    const float* ln1b     = (const float*)d_in[18];
    const float* ln2g     = (const float*)d_in[19];
    const float* ln2b     = (const float*)d_in[20];
    float* out = (float*)d_out;

    float *p_h, *p_buf1, *p_attn, *p_buf2;
    cudaGetSymbolAddress((void**)&p_h,    g_h);
    cudaGetSymbolAddress((void**)&p_buf1, g_buf1);
    cudaGetSymbolAddress((void**)&p_attn, g_attn);
    cudaGetSymbolAddress((void**)&p_buf2, g_buf2);

    cudaFuncSetAttribute(gemm_mma_kernel,
        cudaFuncAttributeMaxDynamicSharedMemorySize, GEMM_SMEM_BYTES);
    cudaFuncSetAttribute(attn_mma_kernel,
        cudaFuncAttributeMaxDynamicSharedMemorySize, ATT_SMEM_BYTES);

    embed_kernel<<<kM, 128>>>(x, t_idx, sp_idx, conv_w, conv_b, pos,
                              time_tab, spat_tab, cls);

    for (int i = 0; i < kLayers; i++) {
        // QKV: [M,128] -> [M,384]
        gemm_mma_kernel<<<dim3(384 / BN, kM / BM), 256, GEMM_SMEM_BYTES>>>(
            p_h, Wqkv + (size_t)i * 384 * kE, bqkv + (size_t)i * 384,
            p_buf1, kM, 384, kE, 0);

        // attention -> g_attn
        attn_mma_kernel<<<kB * kH, 256, ATT_SMEM_BYTES>>>(p_buf1);

        // O-proj: [M,128] -> [M,128]
        gemm_mma_kernel<<<dim3(kE / BN, kM / BM), 256, GEMM_SMEM_BYTES>>>(
            p_attn, Wo + (size_t)i * kE * kE, bo + (size_t)i * kE,
            p_buf2, kM, kE, kE, 0);

        // h = LN(h + o)
        add_ln_kernel<<<kM / 8, 256>>>(p_h, p_buf2,
            ln1g + (size_t)i * kE, ln1b + (size_t)i * kE, p_h);

        // FFN1 + relu: [M,128] -> [M,512]
        gemm_mma_kernel<<<dim3(kFF / BN, kM / BM), 256, GEMM_SMEM_BYTES>>>(
            p_h, W1 + (size_t)i * kFF * kE, b1 + (size_t)i * kFF,
            p_buf1, kM, kFF, kE, 1);

        // FFN2: [M,512] -> [M,128]
        gemm_mma_kernel<<<dim3(kE / BN, kM / BM), 256, GEMM_SMEM_BYTES>>>(
            p_buf1, W2 + (size_t)i * kE * kFF, b2 + (size_t)i * kE,
            p_buf2, kM, kE, kFF, 0);

        // h = LN(h + ff); last layer writes straight to d_out
        float* dst = (i == kLayers - 1) ? out : p_h;
        add_ln_kernel<<<kM / 8, 256>>>(p_h, p_buf2,
            ln2g + (size_t)i * kE, ln2b + (size_t)i * kE, dst);
    }
}

// round 6
// speedup vs baseline: 4.0557x; 1.0226x over previous
#include <cuda_runtime.h>
#include <cuda_bf16.h>
#include <cstdint>

// ---------------- problem constants ----------------
constexpr int kB      = 128;
constexpr int kSeq    = 252;
constexpr int kWin    = 96;
constexpr int kLeads  = 12;
constexpr int kS      = 264;   // kSeq + kLeads
constexpr int kE      = 128;
constexpr int kH      = 8;
constexpr int kD      = 16;    // kE / kH
constexpr int kFF     = 512;
constexpr int kLayers = 12;
constexpr int kM      = kB * kS;   // 33792 tokens

// pair-widths (K/2) for packed bf16 hi/lo activations
constexpr int EP  = kE / 2;    // 64
constexpr int QP  = 192;       // 384/2
constexpr int FP  = kFF / 2;   // 256

// ---------------- scratch (device globals; no allocation allowed) ------------
__device__ float g_h   [kM * kE];   // residual stream (fp32)
__device__ float g_proj[kM * kE];   // O-proj / FFN2 fp32 outputs
// packed bf16 hi/lo activation splits (uint32 = 2 bf16 along K)
__device__ uint32_t g_hh  [kM * EP],  g_hl  [kM * EP];   // h split (QKV/FFN1 in)
__device__ uint32_t g_qkvh[kM * QP],  g_qkvl[kM * QP];   // qkv split (attn in)
__device__ uint32_t g_atth[kM * EP],  g_attl[kM * EP];   // attn out (O-proj in)
__device__ uint32_t g_ff1h[kM * FP],  g_ff1l[kM * FP];   // ff1 out (FFN2 in)
// weight splits
__device__ uint32_t g_wqkvh[kLayers * 384 * EP], g_wqkvl[kLayers * 384 * EP];
__device__ uint32_t g_woh  [kLayers * kE  * EP], g_wol  [kLayers * kE  * EP];
__device__ uint32_t g_w1h  [kLayers * kFF * EP], g_w1l  [kLayers * kFF * EP];
__device__ uint32_t g_w2h  [kLayers * kE  * FP], g_w2l  [kLayers * kE  * FP];

// ---------------- bf16 split helpers ----------------
__device__ __forceinline__ float bhi(float x) {
    return __bfloat162float(__float2bfloat16(x));
}
__device__ __forceinline__ uint32_t packbf(float a, float b) {
    __nv_bfloat162 t;
    t.x = __float2bfloat16(a);
    t.y = __float2bfloat16(b);
    return *reinterpret_cast<uint32_t*>(&t);
}
__device__ __forceinline__ void split2(float a, float b, uint32_t& h, uint32_t& l) {
    float ha = bhi(a), hb = bhi(b);
    h = packbf(a, b);
    l = packbf(a - ha, b - hb);
}

#define MMA_BF16(d, a, b0, b1)                                                \
    asm volatile("mma.sync.aligned.m16n8k16.row.col.f32.bf16.bf16.f32 "       \
                 "{%0,%1,%2,%3}, {%4,%5,%6,%7}, {%8,%9}, {%0,%1,%2,%3};"      \
                 : "+f"(d[0]), "+f"(d[1]), "+f"(d[2]), "+f"(d[3])             \
                 : "r"(a[0]), "r"(a[1]), "r"(a[2]), "r"(a[3]),                \
                   "r"(b0), "r"(b1))

#define MMA_BF16_K8(d, a0, a1, b0)                                            \
    asm volatile("mma.sync.aligned.m16n8k8.row.col.f32.bf16.bf16.f32 "        \
                 "{%0,%1,%2,%3}, {%4,%5}, {%6}, {%0,%1,%2,%3};"               \
                 : "+f"(d[0]), "+f"(d[1]), "+f"(d[2]), "+f"(d[3])             \
                 : "r"(a0), "r"(a1), "r"(b0))

__device__ __forceinline__ void cp16(uint32_t* dst, const uint32_t* src) {
    uint32_t s = (uint32_t)__cvta_generic_to_shared(dst);
    asm volatile("cp.async.ca.shared.global [%0], [%1], 16;" :: "r"(s), "l"(src));
}

// =================== weight split ===================
__global__ __launch_bounds__(256) void wsplit_kernel(
    const float* __restrict__ src, uint32_t* __restrict__ h,
    uint32_t* __restrict__ l, int npairs)
{
    int i = blockIdx.x * 256 + threadIdx.x;
    if (i < npairs) {
        float2 v = *(const float2*)&src[2 * i];
        split2(v.x, v.y, h[i], l[i]);
    }
}

// =================== embedding (writes fp32 h + split) ===================
__global__ __launch_bounds__(128) void embed_kernel(
    const float* __restrict__ x, const int* __restrict__ t_idx,
    const int* __restrict__ sp_idx, const float* __restrict__ conv_w,
    const float* __restrict__ conv_b, const float* __restrict__ pos,
    const float* __restrict__ time_tab, const float* __restrict__ spat_tab,
    const float* __restrict__ cls)
{
    int token = blockIdx.x;
    int b = token / kS, s = token % kS;
    int e = threadIdx.x;
    float val;
    if (s < kLeads) {
        val = cls[s * kE + e] + pos[s * kE + e];
    } else {
        int l = s - kLeads;
        __shared__ float xs[kWin];
        if (e < kWin) xs[e] = x[((size_t)b * kSeq + l) * kWin + e];
        __syncthreads();
        float dot = 0.f;
        #pragma unroll 8
        for (int t = 0; t < kWin; t++) dot += xs[t] * conv_w[e * kWin + t];
        int ti = t_idx [b * kSeq + l];
        int si = sp_idx[b * kSeq + l];
        val = dot + conv_b[e] + pos[s * kE + e]
                  + time_tab[ti * kE + e] + spat_tab[si * kE + e];
    }
    g_h[(size_t)token * kE + e] = val;
    float vn = __shfl_down_sync(0xffffffffu, val, 1);
    if (!(e & 1)) {
        uint32_t h, l2;
        split2(val, vn, h, l2);
        g_hh[(size_t)token * EP + (e >> 1)] = h;
        g_hl[(size_t)token * EP + (e >> 1)] = l2;
    }
}

// =================== bf16x3 GEMM, prepacked operands, cp.async ==============
// C[M,N] = A[M,2*Kp] @ W[N,2*Kp]^T + bias, inputs packed bf16 (h,l) pairs.
// BM=128 BN=64, BKP=16 pairs (K=32) per iter, 256 thr, warp tile 32x32.
// mode: 0 = fp32 out, 1 = split out, 2 = relu + split out.
constexpr int BM = 128, BN = 64, BKP = 16;
constexpr int PSTR = 20;                  // smem row stride (pairs), pad 4
constexpr int GA = BM * PSTR;             // 2560
constexpr int GW = BN * PSTR;             // 1280
constexpr int GBUF = 2 * GA + 2 * GW;     // 7680 words per stage
constexpr int GEMM_SMEM_BYTES = 2 * GBUF * 4;   // 61440

__global__ __launch_bounds__(256) void gemm_mma_kernel(
    const uint32_t* __restrict__ Ah, const uint32_t* __restrict__ Al,
    const uint32_t* __restrict__ Wh, const uint32_t* __restrict__ Wl,
    const float* __restrict__ bias,
    float* __restrict__ Cf, uint32_t* __restrict__ Ch, uint32_t* __restrict__ Cl,
    int M, int N, int Kp, int mode)
{
    extern __shared__ uint32_t gsm[];

    int t = threadIdx.x;
    int bm = blockIdx.y * BM, bn = blockIdx.x * BN;

    // staging mapping
    int saRow = t >> 1;              // 0..127
    int saOfs = (t & 1) * 8;         // 0 or 8
    int swRow = t >> 2;              // 0..63
    int swOfs = (t & 3) * 4;         // 0,4,8,12

    const uint32_t* ahp = Ah + (size_t)(bm + saRow) * Kp + saOfs;
    const uint32_t* alp = Al + (size_t)(bm + saRow) * Kp + saOfs;
    const uint32_t* whp = Wh + (size_t)(bn + swRow) * Kp + swOfs;
    const uint32_t* wlp = Wl + (size_t)(bn + swRow) * Kp + swOfs;

    int wid = t >> 5, lane = t & 31;
    int wm = (wid & 3) * 32;
    int wn = (wid >> 2) * 32;
    int grp = lane >> 2, q = lane & 3;

    float acc[2][4][4] = {};
    int nIter = Kp / BKP;

    // stage 0
    {
        uint32_t* B = gsm;
        cp16(&B[saRow * PSTR + saOfs],            ahp);
        cp16(&B[saRow * PSTR + saOfs + 4],        ahp + 4);
        cp16(&B[GA + saRow * PSTR + saOfs],       alp);
        cp16(&B[GA + saRow * PSTR + saOfs + 4],   alp + 4);
        cp16(&B[2*GA + swRow * PSTR + swOfs],     whp);
        cp16(&B[2*GA + GW + swRow * PSTR + swOfs], wlp);
        asm volatile("cp.async.commit_group;");
    }

    for (int it = 0; it < nIter; it++) {
        if (it + 1 < nIter) {
            uint32_t* B = gsm + ((it + 1) & 1) * GBUF;
            int o = (it + 1) * BKP;
            cp16(&B[saRow * PSTR + saOfs],             ahp + o);
            cp16(&B[saRow * PSTR + saOfs + 4],         ahp + o + 4);
            cp16(&B[GA + saRow * PSTR + saOfs],        alp + o);
            cp16(&B[GA + saRow * PSTR + saOfs + 4],    alp + o + 4);
            cp16(&B[2*GA + swRow * PSTR + swOfs],      whp + o);
            cp16(&B[2*GA + GW + swRow * PSTR + swOfs], wlp + o);
            asm volatile("cp.async.commit_group;");
            asm volatile("cp.async.wait_group 1;");
        } else {
            asm volatile("cp.async.wait_group 0;");
        }
        __syncthreads();

        const uint32_t* B = gsm + (it & 1) * GBUF;
        const uint32_t* AhB = B;
        const uint32_t* AlB = B + GA;
        const uint32_t* WhB = B + 2 * GA;
        const uint32_t* WlB = B + 2 * GA + GW;

        #pragma unroll
        for (int ks = 0; ks < 2; ks++) {
            uint32_t ah[2][4], al[2][4];
            #pragma unroll
            for (int mt = 0; mt < 2; mt++) {
                int rb = (wm + mt * 16 + grp) * PSTR + ks * 8 + q;
                ah[mt][0] = AhB[rb];
                ah[mt][1] = AhB[rb + 8 * PSTR];
                ah[mt][2] = AhB[rb + 4];
                ah[mt][3] = AhB[rb + 8 * PSTR + 4];
                al[mt][0] = AlB[rb];
                al[mt][1] = AlB[rb + 8 * PSTR];
                al[mt][2] = AlB[rb + 4];
                al[mt][3] = AlB[rb + 8 * PSTR + 4];
            }
            #pragma unroll
            for (int nt = 0; nt < 4; nt++) {
                int nb = (wn + nt * 8 + grp) * PSTR + ks * 8 + q;
                uint32_t bh0 = WhB[nb], bh1 = WhB[nb + 4];
                uint32_t bl0 = WlB[nb], bl1 = WlB[nb + 4];
                #pragma unroll
                for (int mt = 0; mt < 2; mt++) {
                    MMA_BF16(acc[mt][nt], ah[mt], bh0, bh1);
                    MMA_BF16(acc[mt][nt], ah[mt], bl0, bl1);
                    MMA_BF16(acc[mt][nt], al[mt], bh0, bh1);
                }
            }
        }
        __syncthreads();
    }

    int Np = N >> 1;
    #pragma unroll
    for (int mt = 0; mt < 2; mt++) {
        int row = bm + wm + mt * 16 + grp;
        #pragma unroll
        for (int nt = 0; nt < 4; nt++) {
            int col = bn + wn + nt * 8 + q * 2;
            float b0 = bias[col], b1 = bias[col + 1];
            float v00 = acc[mt][nt][0] + b0, v01 = acc[mt][nt][1] + b1;
            float v10 = acc[mt][nt][2] + b0, v11 = acc[mt][nt][3] + b1;
            if (mode == 2) {
                v00 = fmaxf(v00, 0.f); v01 = fmaxf(v01, 0.f);
                v10 = fmaxf(v10, 0.f); v11 = fmaxf(v11, 0.f);
            }
            if (mode == 0) {
                float2 o0 = make_float2(v00, v01);
                float2 o1 = make_float2(v10, v11);
                *(float2*)&Cf[(size_t)row * N + col]       = o0;
                *(float2*)&Cf[(size_t)(row + 8) * N + col] = o1;
            } else {
                int pidx = (col >> 1);
                uint32_t h0, l0, h1, l1;
                split2(v00, v01, h0, l0);
                split2(v10, v11, h1, l1);
                Ch[(size_t)row * Np + pidx]       = h0;
                Cl[(size_t)row * Np + pidx]       = l0;
                Ch[(size_t)(row + 8) * Np + pidx] = h1;
                Cl[(size_t)(row + 8) * Np + pidx] = l1;
            }
        }
    }
}

// =================== bf16x3 flash attention, prepacked qkv ===================
// One block per (b,head), 8 warps. K staged as packed pairs along d (stride 12,
// conflict-free); V transposed via byte_perm repack (pairs along kv, stride
// 140). kv = 264 = 33 n8 tiles in 3 chunks of 11. Writes split output.
constexpr int KSTRP = 12;
constexpr int VSTR  = 140;
constexpr int ATT_KWORDS = kS * KSTRP;        // 3168
constexpr int ATT_VWORDS = kD * VSTR;         // 2240
constexpr int ATT_SMEM_BYTES = (2 * ATT_KWORDS + 2 * ATT_VWORDS) * 4;  // 43264

__global__ __launch_bounds__(256, 2) void attn_mma_kernel(
    const uint32_t* __restrict__ qkvh, const uint32_t* __restrict__ qkvl)
{
    extern __shared__ uint32_t asm_[];
    uint32_t* Kh  = asm_;
    uint32_t* Kl  = asm_ + ATT_KWORDS;
    uint32_t* Vth = asm_ + 2 * ATT_KWORDS;
    uint32_t* Vtl = asm_ + 2 * ATT_KWORDS + ATT_VWORDS;

    int bh = blockIdx.x;
    int b = bh >> 3, head = bh & 7;
    int tid = threadIdx.x;
    const size_t tokbase = (size_t)b * kS;

    // stage K: direct packed copy via cp.async (2 x 16B per token row)
    for (int i = tid; i < kS * 2; i += 256) {
        int s = i >> 1, c = (i & 1) * 4;
        const uint32_t* srch = qkvh + (tokbase + s) * QP + 64 + head * 8 + c;
        const uint32_t* srcl = qkvl + (tokbase + s) * QP + 64 + head * 8 + c;
        cp16(&Kh[s * KSTRP + c], srch);
        cp16(&Kl[s * KSTRP + c], srcl);
    }
    asm volatile("cp.async.commit_group;");
    // stage V transposed: repack d-pairs -> kv-pairs with byte_perm
    for (int i = tid; i < 132 * 8; i += 256) {
        int j = i >> 3, pd = i & 7;        // token pair j, d-pair pd
        size_t r0 = (tokbase + 2 * j) * QP + 128 + head * 8 + pd;
        size_t r1 = r0 + QP;
        uint32_t w0h = qkvh[r0], w1h = qkvh[r1];
        uint32_t w0l = qkvl[r0], w1l = qkvl[r1];
        Vth[(2 * pd)     * VSTR + j] = __byte_perm(w0h, w1h, 0x5410);
        Vth[(2 * pd + 1) * VSTR + j] = __byte_perm(w0h, w1h, 0x7632);
        Vtl[(2 * pd)     * VSTR + j] = __byte_perm(w0l, w1l, 0x5410);
        Vtl[(2 * pd + 1) * VSTR + j] = __byte_perm(w0l, w1l, 0x7632);
    }
    asm volatile("cp.async.wait_group 0;");
    __syncthreads();

    int wid = tid >> 5, lane = tid & 31;
    int grp = lane >> 2, q = lane & 3;

    for (int mt = wid; mt < 17; mt += 8) {
        int r0 = mt * 16 + grp;
        int r1 = r0 + 8;
        bool v1 = (r1 < kS);

        // Q m16k16 fragment: direct packed loads (scale folded into scores)
        uint32_t qh[4], ql[4];
        {
            size_t b0 = (tokbase + r0) * QP + head * 8;
            size_t b1 = (tokbase + (v1 ? r1 : r0)) * QP + head * 8;
            qh[0] = qkvh[b0 + q];     ql[0] = qkvl[b0 + q];
            qh[2] = qkvh[b0 + q + 4]; ql[2] = qkvl[b0 + q + 4];
            qh[1] = v1 ? qkvh[b1 + q]     : 0u;
            ql[1] = v1 ? qkvl[b1 + q]     : 0u;
            qh[3] = v1 ? qkvh[b1 + q + 4] : 0u;
            ql[3] = v1 ? qkvl[b1 + q + 4] : 0u;
        }

        float mA = -1e30f, mB = -1e30f, lA = 0.f, lB = 0.f;
        float O[2][4] = {};

        for (int ch = 0; ch < 3; ch++) {
            int n0 = ch * 88;
            int n0h = ch * 44;

            // ---- scores S = Q @ K^T ----
            float sc[11][4];
            #pragma unroll
            for (int nt = 0; nt < 11; nt++) {
                sc[nt][0] = 0.f; sc[nt][1] = 0.f; sc[nt][2] = 0.f; sc[nt][3] = 0.f;
                int kb = (n0 + nt * 8 + grp) * KSTRP + q;
                uint32_t bh0 = Kh[kb], bh1 = Kh[kb + 4];
                uint32_t bl0 = Kl[kb], bl1 = Kl[kb + 4];
                MMA_BF16(sc[nt], qh, bh0, bh1);
                MMA_BF16(sc[nt], qh, bl0, bl1);
                MMA_BF16(sc[nt], ql, bh0, bh1);
            }
            #pragma unroll
            for (int nt = 0; nt < 11; nt++) {
                sc[nt][0] *= 0.25f; sc[nt][1] *= 0.25f;
                sc[nt][2] *= 0.25f; sc[nt][3] *= 0.25f;
            }

            // ---- online softmax ----
            float cmA = -1e30f, cmB = -1e30f;
            #pragma unroll
            for (int nt = 0; nt < 11; nt++) {
                cmA = fmaxf(cmA, fmaxf(sc[nt][0], sc[nt][1]));
                cmB = fmaxf(cmB, fmaxf(sc[nt][2], sc[nt][3]));
            }
            cmA = fmaxf(cmA, __shfl_xor_sync(0xffffffffu, cmA, 1));
            cmA = fmaxf(cmA, __shfl_xor_sync(0xffffffffu, cmA, 2));
            cmB = fmaxf(cmB, __shfl_xor_sync(0xffffffffu, cmB, 1));
            cmB = fmaxf(cmB, __shfl_xor_sync(0xffffffffu, cmB, 2));

            float mnA = fmaxf(mA, cmA), mnB = fmaxf(mB, cmB);
            float aA = __expf(mA - mnA), aB = __expf(mB - mnB);
            mA = mnA; mB = mnB;

            float sA = 0.f, sB = 0.f;
            #pragma unroll
            for (int nt = 0; nt < 11; nt++) {
                sc[nt][0] = __expf(sc[nt][0] - mA);
                sc[nt][1] = __expf(sc[nt][1] - mA);
                sc[nt][2] = __expf(sc[nt][2] - mB);
                sc[nt][3] = __expf(sc[nt][3] - mB);
                sA += sc[nt][0] + sc[nt][1];
                sB += sc[nt][2] + sc[nt][3];
            }
            sA += __shfl_xor_sync(0xffffffffu, sA, 1);
            sA += __shfl_xor_sync(0xffffffffu, sA, 2);
            sB += __shfl_xor_sync(0xffffffffu, sB, 1);
            sB += __shfl_xor_sync(0xffffffffu, sB, 2);
            lA = lA * aA + sA;
            lB = lB * aB + sB;
            #pragma unroll
            for (int n2 = 0; n2 < 2; n2++) {
                O[n2][0] *= aA; O[n2][1] *= aA;
                O[n2][2] *= aB; O[n2][3] *= aB;
            }

            // ---- O += P @ V ----
            #pragma unroll
            for (int kt = 0; kt < 5; kt++) {
                uint32_t pah[4], pal[4];
                split2(sc[2*kt][0],   sc[2*kt][1],   pah[0], pal[0]);
                split2(sc[2*kt][2],   sc[2*kt][3],   pah[1], pal[1]);
                split2(sc[2*kt+1][0], sc[2*kt+1][1], pah[2], pal[2]);
                split2(sc[2*kt+1][2], sc[2*kt+1][3], pah[3], pal[3]);
                int voff = n0h + kt * 8;
                #pragma unroll
                for (int n2 = 0; n2 < 2; n2++) {
                    int vb = (grp + n2 * 8) * VSTR + voff + q;
                    uint32_t bh0 = Vth[vb], bh1 = Vth[vb + 4];
                    uint32_t bl0 = Vtl[vb], bl1 = Vtl[vb + 4];
                    MMA_BF16(O[n2], pah, bh0, bh1);
                    MMA_BF16(O[n2], pah, bl0, bl1);
                    MMA_BF16(O[n2], pal, bh0, bh1);
                }
            }
            {
                uint32_t a0h, a0l, a1h, a1l;
                split2(sc[10][0], sc[10][1], a0h, a0l);
                split2(sc[10][2], sc[10][3], a1h, a1l);
                int voff = n0h + 40;
                #pragma unroll
                for (int n2 = 0; n2 < 2; n2++) {
                    int vb = (grp + n2 * 8) * VSTR + voff + q;
                    uint32_t bh0 = Vth[vb];
                    uint32_t bl0 = Vtl[vb];
                    MMA_BF16_K8(O[n2], a0h, a1h, bh0);
                    MMA_BF16_K8(O[n2], a0h, a1h, bl0);
                    MMA_BF16_K8(O[n2], a0l, a1l, bh0);
                }
            }
        }

        // ---- finalize + split store ----
        float iA = 1.0f / lA, iB = 1.0f / lB;
        #pragma unroll
        for (int n2 = 0; n2 < 2; n2++) {
            int pidx = head * 8 + n2 * 4 + q;
            uint32_t h, l;
            split2(O[n2][0] * iA, O[n2][1] * iA, h, l);
            g_atth[(tokbase + r0) * EP + pidx] = h;
            g_attl[(tokbase + r0) * EP + pidx] = l;
            if (v1) {
                split2(O[n2][2] * iB, O[n2][3] * iB, h, l);
                g_atth[(tokbase + r1) * EP + pidx] = h;
                g_attl[(tokbase + r1) * EP + pidx] = l;
            }
        }
    }
}

// =================== fused residual-add + LayerNorm (+ split out) ============
__global__ __launch_bounds__(256) void add_ln_kernel(
    const float* hin, const float* __restrict__ delta,
    const float* __restrict__ g, const float* __restrict__ beta,
    float* hout, int wsplit)
{
    int row  = blockIdx.x * 8 + (threadIdx.x >> 5);
    int lane = threadIdx.x & 31;
    size_t base = (size_t)row * kE;

    float4 hv = *reinterpret_cast<const float4*>(&hin  [base + lane * 4]);
    float4 dv = *reinterpret_cast<const float4*>(&delta[base + lane * 4]);
    float v0 = hv.x + dv.x, v1 = hv.y + dv.y, v2 = hv.z + dv.z, v3 = hv.w + dv.w;

    float s = v0 + v1 + v2 + v3;
    #pragma unroll
    for (int o = 16; o; o >>= 1) s += __shfl_xor_sync(0xffffffffu, s, o);
    float mean = s * (1.0f / kE);

    float d0 = v0 - mean, d1 = v1 - mean, d2 = v2 - mean, d3 = v3 - mean;
    float sq = d0 * d0 + d1 * d1 + d2 * d2 + d3 * d3;
    #pragma unroll
    for (int o = 16; o; o >>= 1) sq += __shfl_xor_sync(0xffffffffu, sq, o);
    float rstd = rsqrtf(sq * (1.0f / kE) + 1e-5f);

    float4 gv = *reinterpret_cast<const float4*>(&g   [lane * 4]);
    float4 bv = *reinterpret_cast<const float4*>(&beta[lane * 4]);
    float4 ov;
    ov.x = d0 * rstd * gv.x + bv.x;
    ov.y = d1 * rstd * gv.y + bv.y;
    ov.z = d2 * rstd * gv.z + bv.z;
    ov.w = d3 * rstd * gv.w + bv.w;
    *reinterpret_cast<float4*>(&hout[base + lane * 4]) = ov;

    if (wsplit) {
        uint32_t h0, l0, h1, l1;
        split2(ov.x, ov.y, h0, l0);
        split2(ov.z, ov.w, h1, l1);
        size_t pb = (size_t)row * EP + lane * 2;
        g_hh[pb] = h0;     g_hl[pb] = l0;
        g_hh[pb + 1] = h1; g_hl[pb + 1] = l1;
    }
}

// =================== launch ===================
extern "C" void kernel_launch(void* const* d_in, const int* in_sizes, int n_in,
                              void* d_out, int out_size)
{
    const float* x        = (const float*)d_in[0];
    const int*   t_idx    = (const int*)  d_in[1];
    const int*   sp_idx   = (const int*)  d_in[2];
    const float* conv_w   = (const float*)d_in[3];
    const float* conv_b   = (const float*)d_in[4];
    const float* pos      = (const float*)d_in[5];
    const float* time_tab = (const float*)d_in[6];
    const float* spat_tab = (const float*)d_in[7];
    const float* cls      = (const float*)d_in[8];
    const float* Wqkv     = (const float*)d_in[9];
    const float* bqkv     = (const float*)d_in[10];
    const float* Wo       = (const float*)d_in[11];
    const float* bo       = (const float*)d_in[12];
    const float* W1       = (const float*)d_in[13];
    const float* b1       = (const float*)d_in[14];
    const float* W2       = (const float*)d_in[15];
    const float* b2       = (const float*)d_in[16];
    const float* ln1g     = (const float*)d_in[17];
    const float* ln1b     = (const float*)d_in[18];
    const float* ln2g     = (const float*)d_in[19];
    const float* ln2b     = (const float*)d_in[20];
    float* out = (float*)d_out;

    float *p_h, *p_proj;
    uint32_t *p_hh, *p_hl, *p_qkvh, *p_qkvl, *p_atth, *p_attl, *p_ff1h, *p_ff1l;
    uint32_t *p_wqkvh, *p_wqkvl, *p_woh, *p_wol, *p_w1h, *p_w1l, *p_w2h, *p_w2l;
    cudaGetSymbolAddress((void**)&p_h,     g_h);
    cudaGetSymbolAddress((void**)&p_proj,  g_proj);
    cudaGetSymbolAddress((void**)&p_hh,    g_hh);
    cudaGetSymbolAddress((void**)&p_hl,    g_hl);
    cudaGetSymbolAddress((void**)&p_qkvh,  g_qkvh);
    cudaGetSymbolAddress((void**)&p_qkvl,  g_qkvl);
    cudaGetSymbolAddress((void**)&p_atth,  g_atth);
    cudaGetSymbolAddress((void**)&p_attl,  g_attl);
    cudaGetSymbolAddress((void**)&p_ff1h,  g_ff1h);
    cudaGetSymbolAddress((void**)&p_ff1l,  g_ff1l);
    cudaGetSymbolAddress((void**)&p_wqkvh, g_wqkvh);
    cudaGetSymbolAddress((void**)&p_wqkvl, g_wqkvl);
    cudaGetSymbolAddress((void**)&p_woh,   g_woh);
    cudaGetSymbolAddress((void**)&p_wol,   g_wol);
    cudaGetSymbolAddress((void**)&p_w1h,   g_w1h);
    cudaGetSymbolAddress((void**)&p_w1l,   g_w1l);
    cudaGetSymbolAddress((void**)&p_w2h,   g_w2h);
    cudaGetSymbolAddress((void**)&p_w2l,   g_w2l);

    cudaFuncSetAttribute(gemm_mma_kernel,
        cudaFuncAttributeMaxDynamicSharedMemorySize, GEMM_SMEM_BYTES);
    cudaFuncSetAttribute(attn_mma_kernel,
        cudaFuncAttributeMaxDynamicSharedMemorySize, ATT_SMEM_BYTES);

    // one-time weight splits (per launch; graph-capturable kernels)
    {
        int n;
        n = kLayers * 384 * EP;
        wsplit_kernel<<<(n + 255) / 256, 256>>>(Wqkv, p_wqkvh, p_wqkvl, n);
        n = kLayers * kE * EP;
        wsplit_kernel<<<(n + 255) / 256, 256>>>(Wo, p_woh, p_wol, n);
        n = kLayers * kFF * EP;
        wsplit_kernel<<<(n + 255) / 256, 256>>>(W1, p_w1h, p_w1l, n);
        n = kLayers * kE * FP;
        wsplit_kernel<<<(n + 255) / 256, 256>>>(W2, p_w2h, p_w2l, n);
    }

    embed_kernel<<<kM, 128>>>(x, t_idx, sp_idx, conv_w, conv_b, pos,
                              time_tab, spat_tab, cls);

    for (int i = 0; i < kLayers; i++) {
        // QKV: [M,128] -> [M,384]  (split output)
        gemm_mma_kernel<<<dim3(384 / BN, kM / BM), 256, GEMM_SMEM_BYTES>>>(
            p_hh, p_hl, p_wqkvh + (size_t)i * 384 * EP, p_wqkvl + (size_t)i * 384 * EP,
            bqkv + (size_t)i * 384, nullptr, p_qkvh, p_qkvl, kM, 384, EP, 1);

        // attention -> att split
        attn_mma_kernel<<<kB * kH, 256, ATT_SMEM_BYTES>>>(p_qkvh, p_qkvl);

        // O-proj: [M,128] -> [M,128]  (fp32 output)
        gemm_mma_kernel<<<dim3(kE / BN, kM / BM), 256, GEMM_SMEM_BYTES>>>(
            p_atth, p_attl, p_woh + (size_t)i * kE * EP, p_wol + (size_t)i * kE * EP,
            bo + (size_t)i * kE, p_proj, nullptr, nullptr, kM, kE, EP, 0);

        // h = LN(h + o), emit split
        add_ln_kernel<<<kM / 8, 256>>>(p_h, p_proj,
            ln1g + (size_t)i * kE, ln1b + (size_t)i * kE, p_h, 1);

        // FFN1 + relu: [M,128] -> [M,512]  (split output)
        gemm_mma_kernel<<<dim3(kFF / BN, kM / BM), 256, GEMM_SMEM_BYTES>>>(
            p_hh, p_hl, p_w1h + (size_t)i * kFF * EP, p_w1l + (size_t)i * kFF * EP,
            b1 + (size_t)i * kFF, nullptr, p_ff1h, p_ff1l, kM, kFF, EP, 2);

        // FFN2: [M,512] -> [M,128]  (fp32 output)
        gemm_mma_kernel<<<dim3(kE / BN, kM / BM), 256, GEMM_SMEM_BYTES>>>(
            p_ff1h, p_ff1l, p_w2h + (size_t)i * kE * FP, p_w2l + (size_t)i * kE * FP,
            b2 + (size_t)i * kE, p_proj, nullptr, nullptr, kM, kE, FP, 0);

        // h = LN(h + ff); last layer writes d_out (no split needed)
        float* dst = (i == kLayers - 1) ? out : p_h;
        add_ln_kernel<<<kM / 8, 256>>>(p_h, p_proj,
            ln2g + (size_t)i * kE, ln2b + (size_t)i * kE, dst,
            (i == kLayers - 1) ? 0 : 1);
    }
}

// round 8
// speedup vs baseline: 4.3544x; 1.0736x over previous
#include <cuda_runtime.h>
#include <cuda_bf16.h>
#include <cstdint>

// ---------------- problem constants ----------------
constexpr int kB      = 128;
constexpr int kSeq    = 252;
constexpr int kWin    = 96;
constexpr int kLeads  = 12;
constexpr int kS      = 264;   // kSeq + kLeads
constexpr int kE      = 128;
constexpr int kH      = 8;
constexpr int kD      = 16;    // kE / kH
constexpr int kFF     = 512;
constexpr int kLayers = 12;
constexpr int kM      = kB * kS;   // 33792 tokens

// pair-widths (K/2) for packed bf16 hi/lo activations
constexpr int EP  = kE / 2;    // 64
constexpr int QP  = 192;       // 384/2
constexpr int FP  = kFF / 2;   // 256

// ---------------- scratch (device globals; no allocation allowed) ------------
__device__ float g_h   [kM * kE];   // residual stream (fp32)
__device__ float g_proj[kM * kE];   // O-proj / FFN2 fp32 outputs
__device__ uint32_t g_hh  [kM * EP],  g_hl  [kM * EP];
__device__ uint32_t g_qkvh[kM * QP],  g_qkvl[kM * QP];
__device__ uint32_t g_atth[kM * EP],  g_attl[kM * EP];
__device__ uint32_t g_ff1h[kM * FP],  g_ff1l[kM * FP];
__device__ uint32_t g_wqkvh[kLayers * 384 * EP], g_wqkvl[kLayers * 384 * EP];
__device__ uint32_t g_woh  [kLayers * kE  * EP], g_wol  [kLayers * kE  * EP];
__device__ uint32_t g_w1h  [kLayers * kFF * EP], g_w1l  [kLayers * kFF * EP];
__device__ uint32_t g_w2h  [kLayers * kE  * FP], g_w2l  [kLayers * kE  * FP];

// ---------------- bf16 split helpers ----------------
__device__ __forceinline__ float bhi(float x) {
    return __bfloat162float(__float2bfloat16(x));
}
__device__ __forceinline__ uint32_t packbf(float a, float b) {
    __nv_bfloat162 t;
    t.x = __float2bfloat16(a);
    t.y = __float2bfloat16(b);
    return *reinterpret_cast<uint32_t*>(&t);
}
__device__ __forceinline__ void split2(float a, float b, uint32_t& h, uint32_t& l) {
    float ha = bhi(a), hb = bhi(b);
    h = packbf(a, b);
    l = packbf(a - ha, b - hb);
}

#define MMA_BF16(d, a, b0, b1)                                                \
    asm volatile("mma.sync.aligned.m16n8k16.row.col.f32.bf16.bf16.f32 "       \
                 "{%0,%1,%2,%3}, {%4,%5,%6,%7}, {%8,%9}, {%0,%1,%2,%3};"      \
                 : "+f"(d[0]), "+f"(d[1]), "+f"(d[2]), "+f"(d[3])             \
                 : "r"(a[0]), "r"(a[1]), "r"(a[2]), "r"(a[3]),                \
                   "r"(b0), "r"(b1))

#define MMA_BF16_K8(d, a0, a1, b0)                                            \
    asm volatile("mma.sync.aligned.m16n8k8.row.col.f32.bf16.bf16.f32 "        \
                 "{%0,%1,%2,%3}, {%4,%5}, {%6}, {%0,%1,%2,%3};"               \
                 : "+f"(d[0]), "+f"(d[1]), "+f"(d[2]), "+f"(d[3])             \
                 : "r"(a0), "r"(a1), "r"(b0))

#define LDSM_X4(r0, r1, r2, r3, addr)                                         \
    asm volatile("ldmatrix.sync.aligned.m8n8.x4.shared.b16 {%0,%1,%2,%3}, [%4];" \
                 : "=r"(r0), "=r"(r1), "=r"(r2), "=r"(r3) : "r"(addr))

#define LDSM_X2(r0, r1, addr)                                                 \
    asm volatile("ldmatrix.sync.aligned.m8n8.x2.shared.b16 {%0,%1}, [%2];"    \
                 : "=r"(r0), "=r"(r1) : "r"(addr))

__device__ __forceinline__ void cp16(uint32_t* dst, const uint32_t* src) {
    uint32_t s = (uint32_t)__cvta_generic_to_shared(dst);
    asm volatile("cp.async.ca.shared.global [%0], [%1], 16;" :: "r"(s), "l"(src));
}
__device__ __forceinline__ uint32_t smem_u32(const void* p) {
    uint32_t a;
    asm("{ .reg .u64 t; cvta.to.shared.u64 t, %1; cvt.u32.u64 %0, t; }"
        : "=r"(a) : "l"(p));
    return a;
}

// =================== weight split ===================
__global__ __launch_bounds__(256) void wsplit_kernel(
    const float* __restrict__ src, uint32_t* __restrict__ h,
    uint32_t* __restrict__ l, int npairs)
{
    int i = blockIdx.x * 256 + threadIdx.x;
    if (i < npairs) {
        float2 v = *(const float2*)&src[2 * i];
        split2(v.x, v.y, h[i], l[i]);
    }
}

// =================== embedding (writes fp32 h + split) ===================
__global__ __launch_bounds__(128) void embed_kernel(
    const float* __restrict__ x, const int* __restrict__ t_idx,
    const int* __restrict__ sp_idx, const float* __restrict__ conv_w,
    const float* __restrict__ conv_b, const float* __restrict__ pos,
    const float* __restrict__ time_tab, const float* __restrict__ spat_tab,
    const float* __restrict__ cls)
{
    int token = blockIdx.x;
    int b = token / kS, s = token % kS;
    int e = threadIdx.x;
    float val;
    if (s < kLeads) {
        val = cls[s * kE + e] + pos[s * kE + e];
    } else {
        int l = s - kLeads;
        __shared__ float xs[kWin];
        if (e < kWin) xs[e] = x[((size_t)b * kSeq + l) * kWin + e];
        __syncthreads();
        float dot = 0.f;
        #pragma unroll 8
        for (int t = 0; t < kWin; t++) dot += xs[t] * conv_w[e * kWin + t];
        int ti = t_idx [b * kSeq + l];
        int si = sp_idx[b * kSeq + l];
        val = dot + conv_b[e] + pos[s * kE + e]
                  + time_tab[ti * kE + e] + spat_tab[si * kE + e];
    }
    g_h[(size_t)token * kE + e] = val;
    float vn = __shfl_down_sync(0xffffffffu, val, 1);
    if (!(e & 1)) {
        uint32_t h, l2;
        split2(val, vn, h, l2);
        g_hh[(size_t)token * EP + (e >> 1)] = h;
        g_hl[(size_t)token * EP + (e >> 1)] = l2;
    }
}

// =================== bf16x3 GEMM, prepacked, cp.async + ldmatrix =============
// C[M,N] = A[M,2Kp] @ W[N,2Kp]^T + bias, inputs packed bf16 (h,l) pairs.
// BM=128 BN=64, BKP=16 pairs (K=32) per iter, 256 thr, warp tile 32x32.
// Fragments loaded via ldmatrix.x4 (4x fewer shared-load issues).
// mode: 0 = fp32 out, 1 = split out, 2 = relu + split out.
constexpr int BM = 128, BN = 64, BKP = 16;
constexpr int PSTR = 20;                  // smem row stride (pairs), pad 4
constexpr int GA = BM * PSTR;             // 2560
constexpr int GW = BN * PSTR;             // 1280
constexpr int GBUF = 2 * GA + 2 * GW;     // 7680 words per stage
constexpr int GEMM_SMEM_BYTES = 2 * GBUF * 4;   // 61440

__global__ __launch_bounds__(256) void gemm_mma_kernel(
    const uint32_t* __restrict__ Ah, const uint32_t* __restrict__ Al,
    const uint32_t* __restrict__ Wh, const uint32_t* __restrict__ Wl,
    const float* __restrict__ bias,
    float* __restrict__ Cf, uint32_t* __restrict__ Ch, uint32_t* __restrict__ Cl,
    int M, int N, int Kp, int mode)
{
    extern __shared__ uint32_t gsm[];
    uint32_t gsmU = smem_u32(gsm);

    int t = threadIdx.x;
    int bm = blockIdx.y * BM, bn = blockIdx.x * BN;

    // staging mapping
    int saRow = t >> 1;              // 0..127
    int saOfs = (t & 1) * 8;         // 0 or 8
    int swRow = t >> 2;              // 0..63
    int swOfs = (t & 3) * 4;         // 0,4,8,12

    const uint32_t* ahp = Ah + (size_t)(bm + saRow) * Kp + saOfs;
    const uint32_t* alp = Al + (size_t)(bm + saRow) * Kp + saOfs;
    const uint32_t* whp = Wh + (size_t)(bn + swRow) * Kp + swOfs;
    const uint32_t* wlp = Wl + (size_t)(bn + swRow) * Kp + swOfs;

    int wid = t >> 5, lane = t & 31;
    int wm = (wid & 3) * 32;
    int wn = (wid >> 2) * 32;
    int grp = lane >> 2, q = lane & 3;

    // ldmatrix per-lane byte offsets (relative to stage-buffer base)
    uint32_t aOff = (uint32_t)(((wm + (lane & 15)) * PSTR + (lane >> 4) * 4) * 4);
    uint32_t wOff = (uint32_t)((2 * GA + (wn + (lane >> 4) * 8 + (lane & 7)) * PSTR
                                + ((lane >> 3) & 1) * 4) * 4);

    float acc[2][4][4] = {};
    int nIter = Kp / BKP;

    // stage 0
    {
        uint32_t* B = gsm;
        cp16(&B[saRow * PSTR + saOfs],             ahp);
        cp16(&B[saRow * PSTR + saOfs + 4],         ahp + 4);
        cp16(&B[GA + saRow * PSTR + saOfs],        alp);
        cp16(&B[GA + saRow * PSTR + saOfs + 4],    alp + 4);
        cp16(&B[2*GA + swRow * PSTR + swOfs],      whp);
        cp16(&B[2*GA + GW + swRow * PSTR + swOfs], wlp);
        asm volatile("cp.async.commit_group;");
    }

    for (int it = 0; it < nIter; it++) {
        if (it + 1 < nIter) {
            uint32_t* B = gsm + ((it + 1) & 1) * GBUF;
            int o = (it + 1) * BKP;
            cp16(&B[saRow * PSTR + saOfs],             ahp + o);
            cp16(&B[saRow * PSTR + saOfs + 4],         ahp + o + 4);
            cp16(&B[GA + saRow * PSTR + saOfs],        alp + o);
            cp16(&B[GA + saRow * PSTR + saOfs + 4],    alp + o + 4);
            cp16(&B[2*GA + swRow * PSTR + swOfs],      whp + o);
            cp16(&B[2*GA + GW + swRow * PSTR + swOfs], wlp + o);
            asm volatile("cp.async.commit_group;");
            asm volatile("cp.async.wait_group 1;");
        } else {
            asm volatile("cp.async.wait_group 0;");
        }
        __syncthreads();

        uint32_t base = gsmU + (uint32_t)((it & 1) * (GBUF * 4));

        #pragma unroll
        for (int ks = 0; ks < 2; ks++) {
            uint32_t aA = base + aOff + ks * 32;
            uint32_t ah0[4], ah1[4], al0[4], al1[4];
            LDSM_X4(ah0[0], ah0[1], ah0[2], ah0[3], aA);
            LDSM_X4(ah1[0], ah1[1], ah1[2], ah1[3], aA + 16 * PSTR * 4);
            LDSM_X4(al0[0], al0[1], al0[2], al0[3], aA + GA * 4);
            LDSM_X4(al1[0], al1[1], al1[2], al1[3], aA + GA * 4 + 16 * PSTR * 4);

            uint32_t wA = base + wOff + ks * 32;
            uint32_t wh[8], wl[8];
            LDSM_X4(wh[0], wh[1], wh[2], wh[3], wA);
            LDSM_X4(wh[4], wh[5], wh[6], wh[7], wA + 16 * PSTR * 4);
            LDSM_X4(wl[0], wl[1], wl[2], wl[3], wA + GW * 4);
            LDSM_X4(wl[4], wl[5], wl[6], wl[7], wA + GW * 4 + 16 * PSTR * 4);

            #pragma unroll
            for (int nt = 0; nt < 4; nt++) {
                uint32_t bh0 = wh[2 * nt], bh1 = wh[2 * nt + 1];
                uint32_t bl0 = wl[2 * nt], bl1 = wl[2 * nt + 1];
                MMA_BF16(acc[0][nt], ah0, bh0, bh1);
                MMA_BF16(acc[0][nt], ah0, bl0, bl1);
                MMA_BF16(acc[0][nt], al0, bh0, bh1);
                MMA_BF16(acc[1][nt], ah1, bh0, bh1);
                MMA_BF16(acc[1][nt], ah1, bl0, bl1);
                MMA_BF16(acc[1][nt], al1, bh0, bh1);
            }
        }
        __syncthreads();
    }

    int Np = N >> 1;
    #pragma unroll
    for (int mt = 0; mt < 2; mt++) {
        int row = bm + wm + mt * 16 + grp;
        #pragma unroll
        for (int nt = 0; nt < 4; nt++) {
            int col = bn + wn + nt * 8 + q * 2;
            float b0 = bias[col], b1 = bias[col + 1];
            float v00 = acc[mt][nt][0] + b0, v01 = acc[mt][nt][1] + b1;
            float v10 = acc[mt][nt][2] + b0, v11 = acc[mt][nt][3] + b1;
            if (mode == 2) {
                v00 = fmaxf(v00, 0.f); v01 = fmaxf(v01, 0.f);
                v10 = fmaxf(v10, 0.f); v11 = fmaxf(v11, 0.f);
            }
            if (mode == 0) {
                float2 o0 = make_float2(v00, v01);
                float2 o1 = make_float2(v10, v11);
                *(float2*)&Cf[(size_t)row * N + col]       = o0;
                *(float2*)&Cf[(size_t)(row + 8) * N + col] = o1;
            } else {
                int pidx = (col >> 1);
                uint32_t h0, l0, h1, l1;
                split2(v00, v01, h0, l0);
                split2(v10, v11, h1, l1);
                Ch[(size_t)row * Np + pidx]       = h0;
                Cl[(size_t)row * Np + pidx]       = l0;
                Ch[(size_t)(row + 8) * Np + pidx] = h1;
                Cl[(size_t)(row + 8) * Np + pidx] = l1;
            }
        }
    }
}

// =================== bf16x3 flash attention, prepacked qkv, ldmatrix =========
constexpr int KSTRP = 12;
constexpr int VSTR  = 140;
constexpr int ATT_KWORDS = kS * KSTRP;        // 3168
constexpr int ATT_VWORDS = kD * VSTR;         // 2240
constexpr int ATT_SMEM_BYTES = (2 * ATT_KWORDS + 2 * ATT_VWORDS) * 4;  // 43264

__global__ __launch_bounds__(256, 2) void attn_mma_kernel(
    const uint32_t* __restrict__ qkvh, const uint32_t* __restrict__ qkvl)
{
    extern __shared__ uint32_t asm_[];
    uint32_t* Kh  = asm_;
    uint32_t* Kl  = asm_ + ATT_KWORDS;
    uint32_t* Vth = asm_ + 2 * ATT_KWORDS;
    uint32_t* Vtl = asm_ + 2 * ATT_KWORDS + ATT_VWORDS;
    uint32_t KhU  = smem_u32(Kh);
    uint32_t VthU = smem_u32(Vth);

    int bh = blockIdx.x;
    int b = bh >> 3, head = bh & 7;
    int tid = threadIdx.x;
    const size_t tokbase = (size_t)b * kS;

    for (int i = tid; i < kS * 2; i += 256) {
        int s = i >> 1, c = (i & 1) * 4;
        const uint32_t* srch = qkvh + (tokbase + s) * QP + 64 + head * 8 + c;
        const uint32_t* srcl = qkvl + (tokbase + s) * QP + 64 + head * 8 + c;
        cp16(&Kh[s * KSTRP + c], srch);
        cp16(&Kl[s * KSTRP + c], srcl);
    }
    asm volatile("cp.async.commit_group;");
    for (int i = tid; i < 132 * 8; i += 256) {
        int j = i >> 3, pd = i & 7;
        size_t r0 = (tokbase + 2 * j) * QP + 128 + head * 8 + pd;
        size_t r1 = r0 + QP;
        uint32_t w0h = qkvh[r0], w1h = qkvh[r1];
        uint32_t w0l = qkvl[r0], w1l = qkvl[r1];
        Vth[(2 * pd)     * VSTR + j] = __byte_perm(w0h, w1h, 0x5410);
        Vth[(2 * pd + 1) * VSTR + j] = __byte_perm(w0h, w1h, 0x7632);
        Vtl[(2 * pd)     * VSTR + j] = __byte_perm(w0l, w1l, 0x5410);
        Vtl[(2 * pd + 1) * VSTR + j] = __byte_perm(w0l, w1l, 0x7632);
    }
    asm volatile("cp.async.wait_group 0;");
    __syncthreads();

    int wid = tid >> 5, lane = tid & 31;
    int grp = lane >> 2, q = lane & 3;

    // ldmatrix lane offsets
    uint32_t kOff  = (uint32_t)((((lane >> 4) * 8 + (lane & 7)) * KSTRP
                                 + ((lane >> 3) & 1) * 4) * 4);
    uint32_t kOff2 = (uint32_t)(((lane & 7) * KSTRP + ((lane >> 3) & 1) * 4) * 4);
    uint32_t vOff  = (uint32_t)((((lane >> 4) * 8 + (lane & 7)) * VSTR
                                 + ((lane >> 3) & 1) * 4) * 4);
    uint32_t vOff2 = (uint32_t)(((lane & 15) * VSTR) * 4);

    for (int mt = wid; mt < 17; mt += 8) {
        int r0 = mt * 16 + grp;
        int r1 = r0 + 8;
        bool v1 = (r1 < kS);

        uint32_t qh[4], ql[4];
        {
            size_t b0 = (tokbase + r0) * QP + head * 8;
            size_t b1 = (tokbase + (v1 ? r1 : r0)) * QP + head * 8;
            qh[0] = qkvh[b0 + q];     ql[0] = qkvl[b0 + q];
            qh[2] = qkvh[b0 + q + 4]; ql[2] = qkvl[b0 + q + 4];
            qh[1] = v1 ? qkvh[b1 + q]     : 0u;
            ql[1] = v1 ? qkvl[b1 + q]     : 0u;
            qh[3] = v1 ? qkvh[b1 + q + 4] : 0u;
            ql[3] = v1 ? qkvl[b1 + q + 4] : 0u;
        }

        float mA = -1e30f, mB = -1e30f, lA = 0.f, lB = 0.f;
        float O[2][4] = {};

        for (int ch = 0; ch < 3; ch++) {
            int n0 = ch * 88;
            int n0h = ch * 44;

            // ---- scores S = Q @ K^T (ldmatrix.x4 loads 2 n8 tiles) ----
            float sc[11][4];
            #pragma unroll
            for (int nt = 0; nt < 11; nt++) {
                sc[nt][0] = 0.f; sc[nt][1] = 0.f; sc[nt][2] = 0.f; sc[nt][3] = 0.f;
            }
            #pragma unroll
            for (int ntp = 0; ntp < 5; ntp++) {
                uint32_t aH = KhU + kOff + (uint32_t)((n0 + ntp * 16) * KSTRP * 4);
                uint32_t b0h, b1h, b2h, b3h, b0l, b1l, b2l, b3l;
                LDSM_X4(b0h, b1h, b2h, b3h, aH);
                LDSM_X4(b0l, b1l, b2l, b3l, aH + ATT_KWORDS * 4);
                MMA_BF16(sc[2*ntp],   qh, b0h, b1h);
                MMA_BF16(sc[2*ntp],   qh, b0l, b1l);
                MMA_BF16(sc[2*ntp],   ql, b0h, b1h);
                MMA_BF16(sc[2*ntp+1], qh, b2h, b3h);
                MMA_BF16(sc[2*ntp+1], qh, b2l, b3l);
                MMA_BF16(sc[2*ntp+1], ql, b2h, b3h);
            }
            {
                uint32_t aH = KhU + kOff2 + (uint32_t)((n0 + 80) * KSTRP * 4);
                uint32_t b0h, b1h, b0l, b1l;
                LDSM_X2(b0h, b1h, aH);
                LDSM_X2(b0l, b1l, aH + ATT_KWORDS * 4);
                MMA_BF16(sc[10], qh, b0h, b1h);
                MMA_BF16(sc[10], qh, b0l, b1l);
                MMA_BF16(sc[10], ql, b0h, b1h);
            }
            #pragma unroll
            for (int nt = 0; nt < 11; nt++) {
                sc[nt][0] *= 0.25f; sc[nt][1] *= 0.25f;
                sc[nt][2] *= 0.25f; sc[nt][3] *= 0.25f;
            }

            // ---- online softmax ----
            float cmA = -1e30f, cmB = -1e30f;
            #pragma unroll
            for (int nt = 0; nt < 11; nt++) {
                cmA = fmaxf(cmA, fmaxf(sc[nt][0], sc[nt][1]));
                cmB = fmaxf(cmB, fmaxf(sc[nt][2], sc[nt][3]));
            }
            cmA = fmaxf(cmA, __shfl_xor_sync(0xffffffffu, cmA, 1));
            cmA = fmaxf(cmA, __shfl_xor_sync(0xffffffffu, cmA, 2));
            cmB = fmaxf(cmB, __shfl_xor_sync(0xffffffffu, cmB, 1));
            cmB = fmaxf(cmB, __shfl_xor_sync(0xffffffffu, cmB, 2));

            float mnA = fmaxf(mA, cmA), mnB = fmaxf(mB, cmB);
            float aA = __expf(mA - mnA), aB = __expf(mB - mnB);
            mA = mnA; mB = mnB;

            float sA = 0.f, sB = 0.f;
            #pragma unroll
            for (int nt = 0; nt < 11; nt++) {
                sc[nt][0] = __expf(sc[nt][0] - mA);
                sc[nt][1] = __expf(sc[nt][1] - mA);
                sc[nt][2] = __expf(sc[nt][2] - mB);
                sc[nt][3] = __expf(sc[nt][3] - mB);
                sA += sc[nt][0] + sc[nt][1];
                sB += sc[nt][2] + sc[nt][3];
            }
            sA += __shfl_xor_sync(0xffffffffu, sA, 1);
            sA += __shfl_xor_sync(0xffffffffu, sA, 2);
            sB += __shfl_xor_sync(0xffffffffu, sB, 1);
            sB += __shfl_xor_sync(0xffffffffu, sB, 2);
            lA = lA * aA + sA;
            lB = lB * aB + sB;
            #pragma unroll
            for (int n2 = 0; n2 < 2; n2++) {
                O[n2][0] *= aA; O[n2][1] *= aA;
                O[n2][2] *= aB; O[n2][3] *= aB;
            }

            // ---- O += P @ V (ldmatrix.x4 loads both d-halves) ----
            #pragma unroll
            for (int kt = 0; kt < 5; kt++) {
                uint32_t pah[4], pal[4];
                split2(sc[2*kt][0],   sc[2*kt][1],   pah[0], pal[0]);
                split2(sc[2*kt][2],   sc[2*kt][3],   pah[1], pal[1]);
                split2(sc[2*kt+1][0], sc[2*kt+1][1], pah[2], pal[2]);
                split2(sc[2*kt+1][2], sc[2*kt+1][3], pah[3], pal[3]);
                uint32_t vH = VthU + vOff + (uint32_t)((n0h + kt * 8) * 4);
                uint32_t b0h, b1h, b2h, b3h, b0l, b1l, b2l, b3l;
                LDSM_X4(b0h, b1h, b2h, b3h, vH);
                LDSM_X4(b0l, b1l, b2l, b3l, vH + ATT_VWORDS * 4);
                MMA_BF16(O[0], pah, b0h, b1h);
                MMA_BF16(O[0], pah, b0l, b1l);
                MMA_BF16(O[0], pal, b0h, b1h);
                MMA_BF16(O[1], pah, b2h, b3h);
                MMA_BF16(O[1], pah, b2l, b3l);
                MMA_BF16(O[1], pal, b2h, b3h);
            }
            {
                uint32_t a0h, a0l, a1h, a1l;
                split2(sc[10][0], sc[10][1], a0h, a0l);
                split2(sc[10][2], sc[10][3], a1h, a1l);
                uint32_t vH = VthU + vOff2 + (uint32_t)((n0h + 40) * 4);
                uint32_t b0h, b1h, b0l, b1l;
                LDSM_X2(b0h, b1h, vH);
                LDSM_X2(b0l, b1l, vH + ATT_VWORDS * 4);
                MMA_BF16_K8(O[0], a0h, a1h, b0h);
                MMA_BF16_K8(O[0], a0h, a1h, b0l);
                MMA_BF16_K8(O[0], a0l, a1l, b0h);
                MMA_BF16_K8(O[1], a0h, a1h, b1h);
                MMA_BF16_K8(O[1], a0h, a1h, b1l);
                MMA_BF16_K8(O[1], a0l, a1l, b1h);
            }
        }

        float iA = 1.0f / lA, iB = 1.0f / lB;
        #pragma unroll
        for (int n2 = 0; n2 < 2; n2++) {
            int pidx = head * 8 + n2 * 4 + q;
            uint32_t h, l;
            split2(O[n2][0] * iA, O[n2][1] * iA, h, l);
            g_atth[(tokbase + r0) * EP + pidx] = h;
            g_attl[(tokbase + r0) * EP + pidx] = l;
            if (v1) {
                split2(O[n2][2] * iB, O[n2][3] * iB, h, l);
                g_atth[(tokbase + r1) * EP + pidx] = h;
                g_attl[(tokbase + r1) * EP + pidx] = l;
            }
        }
    }
}

// =================== fused residual-add + LayerNorm (+ split out) ============
__global__ __launch_bounds__(256) void add_ln_kernel(
    const float* hin, const float* __restrict__ delta,
    const float* __restrict__ g, const float* __restrict__ beta,
    float* hout, int wsplit)
{
    int row  = blockIdx.x * 8 + (threadIdx.x >> 5);
    int lane = threadIdx.x & 31;
    size_t base = (size_t)row * kE;

    float4 hv = *reinterpret_cast<const float4*>(&hin  [base + lane * 4]);
    float4 dv = *reinterpret_cast<const float4*>(&delta[base + lane * 4]);
    float v0 = hv.x + dv.x, v1 = hv.y + dv.y, v2 = hv.z + dv.z, v3 = hv.w + dv.w;

    float s = v0 + v1 + v2 + v3;
    #pragma unroll
    for (int o = 16; o; o >>= 1) s += __shfl_xor_sync(0xffffffffu, s, o);
    float mean = s * (1.0f / kE);

    float d0 = v0 - mean, d1 = v1 - mean, d2 = v2 - mean, d3 = v3 - mean;
    float sq = d0 * d0 + d1 * d1 + d2 * d2 + d3 * d3;
    #pragma unroll
    for (int o = 16; o; o >>= 1) sq += __shfl_xor_sync(0xffffffffu, sq, o);
    float rstd = rsqrtf(sq * (1.0f / kE) + 1e-5f);

    float4 gv = *reinterpret_cast<const float4*>(&g   [lane * 4]);
    float4 bv = *reinterpret_cast<const float4*>(&beta[lane * 4]);
    float4 ov;
    ov.x = d0 * rstd * gv.x + bv.x;
    ov.y = d1 * rstd * gv.y + bv.y;
    ov.z = d2 * rstd * gv.z + bv.z;
    ov.w = d3 * rstd * gv.w + bv.w;
    *reinterpret_cast<float4*>(&hout[base + lane * 4]) = ov;

    if (wsplit) {
        uint32_t h0, l0, h1, l1;
        split2(ov.x, ov.y, h0, l0);
        split2(ov.z, ov.w, h1, l1);
        size_t pb = (size_t)row * EP + lane * 2;
        g_hh[pb] = h0;     g_hl[pb] = l0;
        g_hh[pb + 1] = h1; g_hl[pb + 1] = l1;
    }
}

// =================== launch ===================
extern "C" void kernel_launch(void* const* d_in, const int* in_sizes, int n_in,
                              void* d_out, int out_size)
{
    const float* x        = (const float*)d_in[0];
    const int*   t_idx    = (const int*)  d_in[1];
    const int*   sp_idx   = (const int*)  d_in[2];
    const float* conv_w   = (const float*)d_in[3];
    const float* conv_b   = (const float*)d_in[4];
    const float* pos      = (const float*)d_in[5];
    const float* time_tab = (const float*)d_in[6];
    const float* spat_tab = (const float*)d_in[7];
    const float* cls      = (const float*)d_in[8];
    const float* Wqkv     = (const float*)d_in[9];
    const float* bqkv     = (const float*)d_in[10];
    const float* Wo       = (const float*)d_in[11];
    const float* bo       = (const float*)d_in[12];
    const float* W1       = (const float*)d_in[13];
    const float* b1       = (const float*)d_in[14];
    const float* W2       = (const float*)d_in[15];
    const float* b2       = (const float*)d_in[16];
    const float* ln1g     = (const float*)d_in[17];
    const float* ln1b     = (const float*)d_in[18];
    const float* ln2g     = (const float*)d_in[19];
    const float* ln2b     = (const float*)d_in[20];
    float* out = (float*)d_out;

    float *p_h, *p_proj;
    uint32_t *p_hh, *p_hl, *p_qkvh, *p_qkvl, *p_atth, *p_attl, *p_ff1h, *p_ff1l;
    uint32_t *p_wqkvh, *p_wqkvl, *p_woh, *p_wol, *p_w1h, *p_w1l, *p_w2h, *p_w2l;
    cudaGetSymbolAddress((void**)&p_h,     g_h);
    cudaGetSymbolAddress((void**)&p_proj,  g_proj);
    cudaGetSymbolAddress((void**)&p_hh,    g_hh);
    cudaGetSymbolAddress((void**)&p_hl,    g_hl);
    cudaGetSymbolAddress((void**)&p_qkvh,  g_qkvh);
    cudaGetSymbolAddress((void**)&p_qkvl,  g_qkvl);
    cudaGetSymbolAddress((void**)&p_atth,  g_atth);
    cudaGetSymbolAddress((void**)&p_attl,  g_attl);
    cudaGetSymbolAddress((void**)&p_ff1h,  g_ff1h);
    cudaGetSymbolAddress((void**)&p_ff1l,  g_ff1l);
    cudaGetSymbolAddress((void**)&p_wqkvh, g_wqkvh);
    cudaGetSymbolAddress((void**)&p_wqkvl, g_wqkvl);
    cudaGetSymbolAddress((void**)&p_woh,   g_woh);
    cudaGetSymbolAddress((void**)&p_wol,   g_wol);
    cudaGetSymbolAddress((void**)&p_w1h,   g_w1h);
    cudaGetSymbolAddress((void**)&p_w1l,   g_w1l);
    cudaGetSymbolAddress((void**)&p_w2h,   g_w2h);
    cudaGetSymbolAddress((void**)&p_w2l,   g_w2l);

    cudaFuncSetAttribute(gemm_mma_kernel,
        cudaFuncAttributeMaxDynamicSharedMemorySize, GEMM_SMEM_BYTES);
    cudaFuncSetAttribute(attn_mma_kernel,
        cudaFuncAttributeMaxDynamicSharedMemorySize, ATT_SMEM_BYTES);

    // one-time weight splits
    {
        int n;
        n = kLayers * 384 * EP;
        wsplit_kernel<<<(n + 255) / 256, 256>>>(Wqkv, p_wqkvh, p_wqkvl, n);
        n = kLayers * kE * EP;
        wsplit_kernel<<<(n + 255) / 256, 256>>>(Wo, p_woh, p_wol, n);
        n = kLayers * kFF * EP;
        wsplit_kernel<<<(n + 255) / 256, 256>>>(W1, p_w1h, p_w1l, n);
        n = kLayers * kE * FP;
        wsplit_kernel<<<(n + 255) / 256, 256>>>(W2, p_w2h, p_w2l, n);
    }

    embed_kernel<<<kM, 128>>>(x, t_idx, sp_idx, conv_w, conv_b, pos,
                              time_tab, spat_tab, cls);

    for (int i = 0; i < kLayers; i++) {
        // QKV: [M,128] -> [M,384]  (split output)
        gemm_mma_kernel<<<dim3(384 / BN, kM / BM), 256, GEMM_SMEM_BYTES>>>(
            p_hh, p_hl, p_wqkvh + (size_t)i * 384 * EP, p_wqkvl + (size_t)i * 384 * EP,
            bqkv + (size_t)i * 384, nullptr, p_qkvh, p_qkvl, kM, 384, EP, 1);

        // attention -> att split
        attn_mma_kernel<<<kB * kH, 256, ATT_SMEM_BYTES>>>(p_qkvh, p_qkvl);

        // O-proj: [M,128] -> [M,128]  (fp32 output)
        gemm_mma_kernel<<<dim3(kE / BN, kM / BM), 256, GEMM_SMEM_BYTES>>>(
            p_atth, p_attl, p_woh + (size_t)i * kE * EP, p_wol + (size_t)i * kE * EP,
            bo + (size_t)i * kE, p_proj, nullptr, nullptr, kM, kE, EP, 0);

        // h = LN(h + o), emit split
        add_ln_kernel<<<kM / 8, 256>>>(p_h, p_proj,
            ln1g + (size_t)i * kE, ln1b + (size_t)i * kE, p_h, 1);

        // FFN1 + relu: [M,128] -> [M,512]  (split output)
        gemm_mma_kernel<<<dim3(kFF / BN, kM / BM), 256, GEMM_SMEM_BYTES>>>(
            p_hh, p_hl, p_w1h + (size_t)i * kFF * EP, p_w1l + (size_t)i * kFF * EP,
            b1 + (size_t)i * kFF, nullptr, p_ff1h, p_ff1l, kM, kFF, EP, 2);

        // FFN2: [M,512] -> [M,128]  (fp32 output)
        gemm_mma_kernel<<<dim3(kE / BN, kM / BM), 256, GEMM_SMEM_BYTES>>>(
            p_ff1h, p_ff1l, p_w2h + (size_t)i * kE * FP, p_w2l + (size_t)i * kE * FP,
            b2 + (size_t)i * kE, p_proj, nullptr, nullptr, kM, kE, FP, 0);

        // h = LN(h + ff); last layer writes d_out
        float* dst = (i == kLayers - 1) ? out : p_h;
        add_ln_kernel<<<kM / 8, 256>>>(p_h, p_proj,
            ln2g + (size_t)i * kE, ln2b + (size_t)i * kE, dst,
            (i == kLayers - 1) ? 0 : 1);
    }
}